// round 12
// baseline (speedup 1.0000x reference)
#include <cuda_runtime.h>
#include <cuda_bf16.h>
#include <math.h>
#include <stdint.h>

#define T_DIM 1024
#define B_DIM 4
#define E_DIM 1024
#define H_DIM 16
#define D_DIM 64
#define RANK_ 4
#define E3 (3*E_DIM)

// ---- device scratch ----
__device__ float g_qkv  [T_DIM*B_DIM*E3];
__device__ float g_rk   [T_DIM*E_DIM];

__device__ __align__(16) __nv_bfloat16 g_in_hi [T_DIM*B_DIM*E_DIM];
__device__ __align__(16) __nv_bfloat16 g_in_lo [T_DIM*B_DIM*E_DIM];
__device__ __align__(16) __nv_bfloat16 g_pos_hi[T_DIM*E_DIM];
__device__ __align__(16) __nv_bfloat16 g_pos_lo[T_DIM*E_DIM];
__device__ __align__(16) __nv_bfloat16 g_ctx_hi[T_DIM*B_DIM*E_DIM];
__device__ __align__(16) __nv_bfloat16 g_ctx_lo[T_DIM*B_DIM*E_DIM];
__device__ __align__(16) __nv_bfloat16 g_win_hi [E3*E_DIM];   // [n][k]
__device__ __align__(16) __nv_bfloat16 g_win_lo [E3*E_DIM];
__device__ __align__(16) __nv_bfloat16 g_wpos_hi[E_DIM*E_DIM];
__device__ __align__(16) __nv_bfloat16 g_wpos_lo[E_DIM*E_DIM];
__device__ __align__(16) __nv_bfloat16 g_wout_hi[E_DIM*E_DIM];
__device__ __align__(16) __nv_bfloat16 g_wout_lo[E_DIM*E_DIM];

// ---- warp-level bf16 MMA ----
__device__ __forceinline__ void mma16816(float* c, const uint32_t* a, const uint32_t* b){
    asm volatile(
        "mma.sync.aligned.m16n8k16.row.col.f32.bf16.bf16.f32 "
        "{%0,%1,%2,%3}, {%4,%5,%6,%7}, {%8,%9}, {%0,%1,%2,%3};"
        : "+f"(c[0]), "+f"(c[1]), "+f"(c[2]), "+f"(c[3])
        : "r"(a[0]), "r"(a[1]), "r"(a[2]), "r"(a[3]), "r"(b[0]), "r"(b[1]));
}

// ---- W' = W + sum_r outer(r,s); output TRANSPOSED [f][e] as bf16 hi/lo ----
__global__ void build_w_bf16(const float* __restrict__ base, const float* __restrict__ rfac,
                             const float* __restrict__ sfac, const int* __restrict__ idx,
                             __nv_bfloat16* __restrict__ whi, __nv_bfloat16* __restrict__ wlo,
                             int F) {
    int lang = idx[0];
    long i = (long)blockIdx.x * blockDim.x + threadIdx.x;
    long total = (long)F * (E_DIM/8);
    if (i >= total) return;
    int f = (int)(i % F);
    int e0 = (int)(i / F) * 8;
    const float* rp = rfac + (long)lang * RANK_ * E_DIM;
    const float* sp = sfac + (long)lang * RANK_ * F;
    float sv[RANK_];
#pragma unroll
    for (int r = 0; r < RANK_; r++) sv[r] = sp[(long)r*F + f];
    __nv_bfloat16 h8[8], l8[8];
#pragma unroll
    for (int j = 0; j < 8; j++) {
        int e = e0 + j;
        float v = base[(long)e*F + f];
#pragma unroll
        for (int r = 0; r < RANK_; r++) v = fmaf(rp[r*E_DIM + e], sv[r], v);
        __nv_bfloat16 h = __float2bfloat16(v);
        h8[j] = h;
        l8[j] = __float2bfloat16(v - __bfloat162float(h));
    }
    *(uint4*)&whi[(long)f*E_DIM + e0] = *(uint4*)h8;
    *(uint4*)&wlo[(long)f*E_DIM + e0] = *(uint4*)l8;
}

// ---- fp32 -> bf16 hi/lo split ----
__global__ void conv_bf16(const float* __restrict__ x, __nv_bfloat16* __restrict__ hi,
                          __nv_bfloat16* __restrict__ lo, int n) {
    int i = (blockIdx.x*blockDim.x + threadIdx.x) * 4;
    if (i >= n) return;
    float4 v = *(const float4*)&x[i];
    float vv[4] = {v.x, v.y, v.z, v.w};
    __nv_bfloat16 h4[4], l4[4];
#pragma unroll
    for (int j = 0; j < 4; j++) {
        __nv_bfloat16 h = __float2bfloat16(vv[j]);
        h4[j] = h;
        l4[j] = __float2bfloat16(vv[j] - __bfloat162float(h));
    }
    *(uint2*)&hi[i] = *(uint2*)h4;
    *(uint2*)&lo[i] = *(uint2*)l4;
}

// ---- HMMA bf16-split GEMM: C[M,N] = A[M,K] @ B[N,K]^T + bias ----
#define SA 56

__global__ __launch_bounds__(256, 2)
void gemm_mma(const __nv_bfloat16* __restrict__ Ahi, const __nv_bfloat16* __restrict__ Alo,
              const __nv_bfloat16* __restrict__ Bhi, const __nv_bfloat16* __restrict__ Blo,
              const float* __restrict__ bias, float* __restrict__ C, int N_) {
    __shared__ __align__(16) __nv_bfloat16 sAh[128*SA];
    __shared__ __align__(16) __nv_bfloat16 sAl[128*SA];
    __shared__ __align__(16) __nv_bfloat16 sBh[64*SA];
    __shared__ __align__(16) __nv_bfloat16 sBl[64*SA];

    const int K = E_DIM;
    int tid = threadIdx.x;
    int wid = tid >> 5, lid = tid & 31;
    int warpM = wid & 3, warpN = wid >> 2;
    long m0 = (long)blockIdx.y * 128, n0 = (long)blockIdx.x * 64;

    int gRow = lid >> 2;
    int cPair = (lid & 3) * 2;

    const int ap0 = tid, ap1 = tid + 256;
    const int ar0 = ap0 >> 2, aq0 = ap0 & 3;
    const int ar1 = ap1 >> 2, aq1 = ap1 & 3;
    const int br = tid >> 2, bq = tid & 3;

    float acc[2][4][4];
#pragma unroll
    for (int mt = 0; mt < 2; mt++)
#pragma unroll
        for (int nt = 0; nt < 4; nt++)
#pragma unroll
            for (int q = 0; q < 4; q++) acc[mt][nt][q] = 0.f;

    uint4 pah0 = *(const uint4*)&Ahi[(m0+ar0)*K + aq0*8];
    uint4 pah1 = *(const uint4*)&Ahi[(m0+ar1)*K + aq1*8];
    uint4 pal0 = *(const uint4*)&Alo[(m0+ar0)*K + aq0*8];
    uint4 pal1 = *(const uint4*)&Alo[(m0+ar1)*K + aq1*8];
    uint4 pbh  = *(const uint4*)&Bhi[(n0+br)*K + bq*8];
    uint4 pbl  = *(const uint4*)&Blo[(n0+br)*K + bq*8];

    for (int kc = 0; kc < K; kc += 32) {
        *(uint4*)&sAh[ar0*SA + aq0*8] = pah0;
        *(uint4*)&sAh[ar1*SA + aq1*8] = pah1;
        *(uint4*)&sAl[ar0*SA + aq0*8] = pal0;
        *(uint4*)&sAl[ar1*SA + aq1*8] = pal1;
        *(uint4*)&sBh[br*SA + bq*8] = pbh;
        *(uint4*)&sBl[br*SA + bq*8] = pbl;
        __syncthreads();

        if (kc + 32 < K) {
            int kn = kc + 32;
            pah0 = *(const uint4*)&Ahi[(m0+ar0)*K + kn + aq0*8];
            pah1 = *(const uint4*)&Ahi[(m0+ar1)*K + kn + aq1*8];
            pal0 = *(const uint4*)&Alo[(m0+ar0)*K + kn + aq0*8];
            pal1 = *(const uint4*)&Alo[(m0+ar1)*K + kn + aq1*8];
            pbh  = *(const uint4*)&Bhi[(n0+br)*K + kn + bq*8];
            pbl  = *(const uint4*)&Blo[(n0+br)*K + kn + bq*8];
        }

#pragma unroll
        for (int ks = 0; ks < 2; ks++) {
            int kb = ks * 16;
            uint32_t ah[2][4], al[2][4], bh[4][2], bl[4][2];
#pragma unroll
            for (int mt = 0; mt < 2; mt++) {
                int r = warpM*32 + mt*16 + gRow;
                ah[mt][0] = *(uint32_t*)&sAh[r*SA + kb + cPair];
                ah[mt][1] = *(uint32_t*)&sAh[(r+8)*SA + kb + cPair];
                ah[mt][2] = *(uint32_t*)&sAh[r*SA + kb + cPair + 8];
                ah[mt][3] = *(uint32_t*)&sAh[(r+8)*SA + kb + cPair + 8];
                al[mt][0] = *(uint32_t*)&sAl[r*SA + kb + cPair];
                al[mt][1] = *(uint32_t*)&sAl[(r+8)*SA + kb + cPair];
                al[mt][2] = *(uint32_t*)&sAl[r*SA + kb + cPair + 8];
                al[mt][3] = *(uint32_t*)&sAl[(r+8)*SA + kb + cPair + 8];
            }
#pragma unroll
            for (int nt = 0; nt < 4; nt++) {
                int n = warpN*32 + nt*8 + gRow;
                bh[nt][0] = *(uint32_t*)&sBh[n*SA + kb + cPair];
                bh[nt][1] = *(uint32_t*)&sBh[n*SA + kb + cPair + 8];
                bl[nt][0] = *(uint32_t*)&sBl[n*SA + kb + cPair];
                bl[nt][1] = *(uint32_t*)&sBl[n*SA + kb + cPair + 8];
            }
#pragma unroll
            for (int mt = 0; mt < 2; mt++)
#pragma unroll
                for (int nt = 0; nt < 4; nt++) {
                    mma16816(acc[mt][nt], ah[mt], bh[nt]);
                    mma16816(acc[mt][nt], ah[mt], bl[nt]);
                    mma16816(acc[mt][nt], al[mt], bh[nt]);
                }
        }
        __syncthreads();
    }

#pragma unroll
    for (int mt = 0; mt < 2; mt++) {
        long r0 = m0 + warpM*32 + mt*16 + gRow;
#pragma unroll
        for (int nt = 0; nt < 4; nt++) {
            long n = n0 + warpN*32 + nt*8 + cPair;
            float2 bia = *(const float2*)&bias[n];
            float2 o0 = { acc[mt][nt][0] + bia.x, acc[mt][nt][1] + bia.y };
            float2 o1 = { acc[mt][nt][2] + bia.x, acc[mt][nt][3] + bia.y };
            *(float2*)&C[r0*N_ + n] = o0;
            *(float2*)&C[(r0+8)*N_ + n] = o1;
        }
    }
}

// ---- fused relative attention ----
#define QSTR 68
#define RSTR 132

// MODE 0: all delta <= 0 (use arv[r]); MODE 1: all delta >= 1 (use arv[r+1]); MODE 2: mixed
template<int MODE>
__device__ __forceinline__ void qk_accum(const float* qw, const float* qr, const float* kt,
                                         const float* rks, int ty, int tx, int mm15,
                                         int d0, float s[4][4]) {
    for (int d = 0; d < 64; d++) {
        float4 aw = *(const float4*)&qw[d*QSTR + ty*4];
        float4 a4 = *(const float4*)&qr[d*QSTR + ty*4];
        float  a5 = qr[d*QSTR + ty*4 + 4];
        float4 bk = *(const float4*)&kt[d*QSTR + tx*4];
        float4 r0 = *(const float4*)&rks[d*RSTR + 4*mm15];
        float4 r1 = *(const float4*)&rks[d*RSTR + 4*mm15 + 4];
        float awv[4] = {aw.x, aw.y, aw.z, aw.w};
        float arv[5] = {a4.x, a4.y, a4.z, a4.w, a5};
        float bkv[4] = {bk.x, bk.y, bk.z, bk.w};
        float rv[7]  = {r0.x, r0.y, r0.z, r0.w, r1.x, r1.y, r1.z};
#pragma unroll
        for (int r = 0; r < 4; r++)
#pragma unroll
            for (int c = 0; c < 4; c++) {
                float av;
                if (MODE == 0)      av = arv[r];
                else if (MODE == 1) av = arv[r+1];
                else                av = (d0 + c - r <= 0) ? arv[r] : arv[r+1];
                s[r][c] += awv[r]*bkv[c] + av*rv[c - r + 3];
            }
    }
}

__global__ __launch_bounds__(256, 2)
void attn_kernel(const float* __restrict__ qkv, const float* __restrict__ rk,
                 const unsigned char* __restrict__ mask,
                 const float* __restrict__ rwb, const float* __restrict__ rrb,
                 __nv_bfloat16* __restrict__ ctx_hi, __nv_bfloat16* __restrict__ ctx_lo) {
    extern __shared__ float sm[];
    float* qw  = sm;
    float* qr  = qw  + 64*QSTR;
    float* kt  = qr  + 64*QSTR;
    float* vt  = kt  + 64*QSTR;
    float* rks = vt  + 4096;
    float* ps  = kt;

    int tx = threadIdx.x, ty = threadIdx.y;
    int tid = ty*16 + tx;
    int i0 = blockIdx.x*64;
    int h = blockIdx.y, b = blockIdx.z;
    const float scale = 0.125f;

    for (int e = tid; e < 65*16; e += 256) {
        int ii = e >> 4, d4 = (e & 15) * 4;
        int t = i0 + ii;
        float4 qv = make_float4(0.f,0.f,0.f,0.f);
        if (t < T_DIM)
            qv = *(const float4*)&qkv[(long)(t*B_DIM + b)*E3 + h*D_DIM + d4];
        float4 wb = *(const float4*)&rwb[h*D_DIM + d4];
        float4 rb = *(const float4*)&rrb[h*D_DIM + d4];
        if (ii < 64) {
            qw[(d4+0)*QSTR + ii] = qv.x + wb.x;
            qw[(d4+1)*QSTR + ii] = qv.y + wb.y;
            qw[(d4+2)*QSTR + ii] = qv.z + wb.z;
            qw[(d4+3)*QSTR + ii] = qv.w + wb.w;
        }
        qr[(d4+0)*QSTR + ii] = qv.x + rb.x;
        qr[(d4+1)*QSTR + ii] = qv.y + rb.y;
        qr[(d4+2)*QSTR + ii] = qv.z + rb.z;
        qr[(d4+3)*QSTR + ii] = qv.w + rb.w;
    }

    float m[4], l[4], acc[4][4];
#pragma unroll
    for (int r = 0; r < 4; r++) {
        m[r] = -1e30f; l[r] = 0.f;
#pragma unroll
        for (int c = 0; c < 4; c++) acc[r][c] = 0.f;
    }

    const int mm15 = 15 + tx - ty;

    for (int j0 = 0; j0 < T_DIM; j0 += 64) {
        __syncthreads();
        for (int e = tid; e < 64*16; e += 256) {
            int jj = e >> 4, d4 = (e & 15) * 4;
            long off = (long)((j0+jj)*B_DIM + b)*E3 + h*D_DIM + d4;
            float4 kv = *(const float4*)&qkv[off + E_DIM];
            float4 vv = *(const float4*)&qkv[off + 2*E_DIM];
            kt[(d4+0)*QSTR + jj] = kv.x;
            kt[(d4+1)*QSTR + jj] = kv.y;
            kt[(d4+2)*QSTR + jj] = kv.z;
            kt[(d4+3)*QSTR + jj] = kv.w;
            *(float4*)&vt[jj*64 + d4] = vv;
        }
        int base = j0 - i0;
        for (int e = tid; e < 127*16; e += 256) {
            int w = e >> 4, d4 = (e & 15) * 4;
            int delta = base - 63 + w;
            float4 v = make_float4(0.f,0.f,0.f,0.f);
            if (delta <= 0)      v = *(const float4*)&rk[(long)(T_DIM - 1 + delta)*E_DIM + h*D_DIM + d4];
            else if (delta >= 2) v = *(const float4*)&rk[(long)(delta - 2)*E_DIM + h*D_DIM + d4];
            rks[(d4+0)*RSTR + w] = v.x;
            rks[(d4+1)*RSTR + w] = v.y;
            rks[(d4+2)*RSTR + w] = v.z;
            rks[(d4+3)*RSTR + w] = v.w;
        }
        __syncthreads();

        float s[4][4];
#pragma unroll
        for (int r = 0; r < 4; r++)
#pragma unroll
            for (int c = 0; c < 4; c++) s[r][c] = 0.f;

        const int d0 = base + 4*(tx - ty);

        // delta = d0 + c - r spans [base-63, base+63]; base is a multiple of 64,
        // so only base==0 is mixed.
        if (base < 0)        qk_accum<0>(qw, qr, kt, rks, ty, tx, mm15, d0, s);
        else if (base >= 64) qk_accum<1>(qw, qr, kt, rks, ty, tx, mm15, d0, s);
        else                 qk_accum<2>(qw, qr, kt, rks, ty, tx, mm15, d0, s);
        __syncthreads();

#pragma unroll
        for (int c = 0; c < 4; c++) {
            bool mk = mask[b*T_DIM + j0 + tx*4 + c] != 0;
#pragma unroll
            for (int r = 0; r < 4; r++) {
                s[r][c] *= scale;
                if (mk) s[r][c] = -1e9f;
            }
        }

#pragma unroll
        for (int r = 0; r < 4; r++) {
            float mx = s[r][0];
#pragma unroll
            for (int c = 1; c < 4; c++) mx = fmaxf(mx, s[r][c]);
#pragma unroll
            for (int off = 8; off >= 1; off >>= 1)
                mx = fmaxf(mx, __shfl_xor_sync(0xffffffffu, mx, off, 16));
            float mnew = fmaxf(m[r], mx);
            float corr = __expf(m[r] - mnew);
            float4 p4;
            p4.x = __expf(s[r][0] - mnew);
            p4.y = __expf(s[r][1] - mnew);
            p4.z = __expf(s[r][2] - mnew);
            p4.w = __expf(s[r][3] - mnew);
            float rs = p4.x + p4.y + p4.z + p4.w;
            *(float4*)&ps[(ty*4+r)*QSTR + tx*4] = p4;
#pragma unroll
            for (int off = 8; off >= 1; off >>= 1)
                rs += __shfl_xor_sync(0xffffffffu, rs, off, 16);
            l[r] = l[r]*corr + rs;
            m[r] = mnew;
#pragma unroll
            for (int c = 0; c < 4; c++) acc[r][c] *= corr;
        }
        __syncthreads();

        for (int jj = 0; jj < 64; jj++) {
            float pv[4];
#pragma unroll
            for (int r = 0; r < 4; r++) pv[r] = ps[(ty*4+r)*QSTR + jj];
            float4 vv = *(float4*)&vt[jj*64 + tx*4];
            float vvv[4] = {vv.x, vv.y, vv.z, vv.w};
#pragma unroll
            for (int r = 0; r < 4; r++)
#pragma unroll
                for (int c = 0; c < 4; c++)
                    acc[r][c] = fmaf(pv[r], vvv[c], acc[r][c]);
        }
    }

    // epilogue: write bf16 hi/lo split directly (packed 4x bf16 per store)
#pragma unroll
    for (int r = 0; r < 4; r++) {
        float inv = 1.f / l[r];
        int t = i0 + ty*4 + r;
        long o = (long)(t*B_DIM + b)*E_DIM + h*D_DIM + tx*4;
        __nv_bfloat16 h4[4], l4[4];
#pragma unroll
        for (int c = 0; c < 4; c++) {
            float v = acc[r][c]*inv;
            __nv_bfloat16 hh = __float2bfloat16(v);
            h4[c] = hh;
            l4[c] = __float2bfloat16(v - __bfloat162float(hh));
        }
        *(uint2*)&ctx_hi[o] = *(uint2*)h4;
        *(uint2*)&ctx_lo[o] = *(uint2*)l4;
    }
}

#define ATTN_SMEM ((3*64*QSTR + 4096 + 64*RSTR) * 4)

extern "C" void kernel_launch(void* const* d_in, const int* in_sizes, int n_in,
                              void* d_out, int out_size) {
    const float* input   = (const float*)d_in[0];
    const float* pos     = (const float*)d_in[1];
    const int*   indices = (const int*)  d_in[2];
    const unsigned char* mask = (const unsigned char*)d_in[3];
    const float* in_w  = (const float*)d_in[4];
    const float* pos_w = (const float*)d_in[5];
    const float* out_w = (const float*)d_in[6];
    const float* in_b  = (const float*)d_in[7];
    const float* pos_b = (const float*)d_in[8];
    const float* out_b = (const float*)d_in[9];
    const float* r_i = (const float*)d_in[10];
    const float* s_i = (const float*)d_in[11];
    const float* r_p = (const float*)d_in[12];
    const float* s_p = (const float*)d_in[13];
    const float* r_o = (const float*)d_in[14];
    const float* s_o = (const float*)d_in[15];
    const float* rwb = (const float*)d_in[16];
    const float* rrb = (const float*)d_in[17];
    float* out = (float*)d_out;

    float *qkv, *rk;
    __nv_bfloat16 *in_hi, *in_lo, *pos_hi, *pos_lo, *ctx_hi, *ctx_lo;
    __nv_bfloat16 *win_hi, *win_lo, *wpos_hi, *wpos_lo, *wout_hi, *wout_lo;
    cudaGetSymbolAddress((void**)&qkv,   g_qkv);
    cudaGetSymbolAddress((void**)&rk,    g_rk);
    cudaGetSymbolAddress((void**)&in_hi, g_in_hi);
    cudaGetSymbolAddress((void**)&in_lo, g_in_lo);
    cudaGetSymbolAddress((void**)&pos_hi,g_pos_hi);
    cudaGetSymbolAddress((void**)&pos_lo,g_pos_lo);
    cudaGetSymbolAddress((void**)&ctx_hi,g_ctx_hi);
    cudaGetSymbolAddress((void**)&ctx_lo,g_ctx_lo);
    cudaGetSymbolAddress((void**)&win_hi,g_win_hi);
    cudaGetSymbolAddress((void**)&win_lo,g_win_lo);
    cudaGetSymbolAddress((void**)&wpos_hi,g_wpos_hi);
    cudaGetSymbolAddress((void**)&wpos_lo,g_wpos_lo);
    cudaGetSymbolAddress((void**)&wout_hi,g_wout_hi);
    cudaGetSymbolAddress((void**)&wout_lo,g_wout_lo);

    const int thr = 256;
    build_w_bf16<<<(E3*(E_DIM/8) + thr-1)/thr, thr>>>(in_w,  r_i, s_i, indices, win_hi,  win_lo,  E3);
    build_w_bf16<<<(E_DIM*(E_DIM/8) + thr-1)/thr, thr>>>(pos_w, r_p, s_p, indices, wpos_hi, wpos_lo, E_DIM);
    build_w_bf16<<<(E_DIM*(E_DIM/8) + thr-1)/thr, thr>>>(out_w, r_o, s_o, indices, wout_hi, wout_lo, E_DIM);
    conv_bf16<<<(T_DIM*B_DIM*E_DIM/4 + thr-1)/thr, thr>>>(input, in_hi, in_lo, T_DIM*B_DIM*E_DIM);
    conv_bf16<<<(T_DIM*E_DIM/4 + thr-1)/thr, thr>>>(pos, pos_hi, pos_lo, T_DIM*E_DIM);

    gemm_mma<<<dim3(E3/64, (T_DIM*B_DIM)/128), 256>>>(in_hi, in_lo, win_hi, win_lo, in_b, qkv, E3);
    gemm_mma<<<dim3(E_DIM/64, T_DIM/128), 256>>>(pos_hi, pos_lo, wpos_hi, wpos_lo, pos_b, rk, E_DIM);

    cudaFuncSetAttribute(attn_kernel, cudaFuncAttributeMaxDynamicSharedMemorySize, ATTN_SMEM);
    attn_kernel<<<dim3(T_DIM/64, H_DIM, B_DIM), dim3(16,16), ATTN_SMEM>>>(qkv, rk, mask, rwb, rrb, ctx_hi, ctx_lo);

    gemm_mma<<<dim3(E_DIM/64, (T_DIM*B_DIM)/128), 256>>>(ctx_hi, ctx_lo, wout_hi, wout_lo, out_b, out, E_DIM);
}

// round 13
// speedup vs baseline: 1.0438x; 1.0438x over previous
#include <cuda_runtime.h>
#include <cuda_bf16.h>
#include <math.h>
#include <stdint.h>

#define T_DIM 1024
#define B_DIM 4
#define E_DIM 1024
#define H_DIM 16
#define D_DIM 64
#define RANK_ 4
#define E3 (3*E_DIM)

// ---- device scratch ----
__device__ float g_qkv  [T_DIM*B_DIM*E3];
__device__ float g_rk   [T_DIM*E_DIM];

__device__ __align__(16) __nv_bfloat16 g_in_hi [T_DIM*B_DIM*E_DIM];
__device__ __align__(16) __nv_bfloat16 g_in_lo [T_DIM*B_DIM*E_DIM];
__device__ __align__(16) __nv_bfloat16 g_pos_hi[T_DIM*E_DIM];
__device__ __align__(16) __nv_bfloat16 g_pos_lo[T_DIM*E_DIM];
__device__ __align__(16) __nv_bfloat16 g_ctx_hi[T_DIM*B_DIM*E_DIM];
__device__ __align__(16) __nv_bfloat16 g_ctx_lo[T_DIM*B_DIM*E_DIM];
__device__ __align__(16) __nv_bfloat16 g_win_hi [E3*E_DIM];   // [n][k]
__device__ __align__(16) __nv_bfloat16 g_win_lo [E3*E_DIM];
__device__ __align__(16) __nv_bfloat16 g_wpos_hi[E_DIM*E_DIM];
__device__ __align__(16) __nv_bfloat16 g_wpos_lo[E_DIM*E_DIM];
__device__ __align__(16) __nv_bfloat16 g_wout_hi[E_DIM*E_DIM];
__device__ __align__(16) __nv_bfloat16 g_wout_lo[E_DIM*E_DIM];

// ---- warp-level bf16 MMA (family-common; verified passing in gemm_mma) ----
__device__ __forceinline__ void mma16816(float* c, const uint32_t* a, const uint32_t* b){
    asm volatile(
        "mma.sync.aligned.m16n8k16.row.col.f32.bf16.bf16.f32 "
        "{%0,%1,%2,%3}, {%4,%5,%6,%7}, {%8,%9}, {%0,%1,%2,%3};"
        : "+f"(c[0]), "+f"(c[1]), "+f"(c[2]), "+f"(c[3])
        : "r"(a[0]), "r"(a[1]), "r"(a[2]), "r"(a[3]), "r"(b[0]), "r"(b[1]));
}

__device__ __forceinline__ void split2(float a, float b, uint32_t& hi, uint32_t& lo){
    __nv_bfloat16 ah = __float2bfloat16(a), bh = __float2bfloat16(b);
    __nv_bfloat16 al = __float2bfloat16(a - __bfloat162float(ah));
    __nv_bfloat16 bl = __float2bfloat16(b - __bfloat162float(bh));
    __nv_bfloat162 H; H.x = ah; H.y = bh;
    __nv_bfloat162 L; L.x = al; L.y = bl;
    hi = *(uint32_t*)&H; lo = *(uint32_t*)&L;
}

__device__ __forceinline__ void put_hl(__nv_bfloat16* ph, __nv_bfloat16* pl, int idx, float v){
    __nv_bfloat16 h = __float2bfloat16(v);
    ph[idx] = h;
    pl[idx] = __float2bfloat16(v - __bfloat162float(h));
}

// ---- W' = W + sum_r outer(r,s); output TRANSPOSED [f][e] as bf16 hi/lo ----
__global__ void build_w_bf16(const float* __restrict__ base, const float* __restrict__ rfac,
                             const float* __restrict__ sfac, const int* __restrict__ idx,
                             __nv_bfloat16* __restrict__ whi, __nv_bfloat16* __restrict__ wlo,
                             int F) {
    int lang = idx[0];
    long i = (long)blockIdx.x * blockDim.x + threadIdx.x;
    long total = (long)F * (E_DIM/8);
    if (i >= total) return;
    int f = (int)(i % F);
    int e0 = (int)(i / F) * 8;
    const float* rp = rfac + (long)lang * RANK_ * E_DIM;
    const float* sp = sfac + (long)lang * RANK_ * F;
    float sv[RANK_];
#pragma unroll
    for (int r = 0; r < RANK_; r++) sv[r] = sp[(long)r*F + f];
    __nv_bfloat16 h8[8], l8[8];
#pragma unroll
    for (int j = 0; j < 8; j++) {
        int e = e0 + j;
        float v = base[(long)e*F + f];
#pragma unroll
        for (int r = 0; r < RANK_; r++) v = fmaf(rp[r*E_DIM + e], sv[r], v);
        __nv_bfloat16 h = __float2bfloat16(v);
        h8[j] = h;
        l8[j] = __float2bfloat16(v - __bfloat162float(h));
    }
    *(uint4*)&whi[(long)f*E_DIM + e0] = *(uint4*)h8;
    *(uint4*)&wlo[(long)f*E_DIM + e0] = *(uint4*)l8;
}

// ---- fp32 -> bf16 hi/lo split ----
__global__ void conv_bf16(const float* __restrict__ x, __nv_bfloat16* __restrict__ hi,
                          __nv_bfloat16* __restrict__ lo, int n) {
    int i = (blockIdx.x*blockDim.x + threadIdx.x) * 4;
    if (i >= n) return;
    float4 v = *(const float4*)&x[i];
    float vv[4] = {v.x, v.y, v.z, v.w};
    __nv_bfloat16 h4[4], l4[4];
#pragma unroll
    for (int j = 0; j < 4; j++) {
        __nv_bfloat16 h = __float2bfloat16(vv[j]);
        h4[j] = h;
        l4[j] = __float2bfloat16(vv[j] - __bfloat162float(h));
    }
    *(uint2*)&hi[i] = *(uint2*)h4;
    *(uint2*)&lo[i] = *(uint2*)l4;
}

// ---- HMMA bf16-split GEMM: C[M,N] = A[M,K] @ B[N,K]^T + bias (unchanged, passing) ----
#define SA 56

__global__ __launch_bounds__(256, 2)
void gemm_mma(const __nv_bfloat16* __restrict__ Ahi, const __nv_bfloat16* __restrict__ Alo,
              const __nv_bfloat16* __restrict__ Bhi, const __nv_bfloat16* __restrict__ Blo,
              const float* __restrict__ bias, float* __restrict__ C, int N_) {
    __shared__ __align__(16) __nv_bfloat16 sAh[128*SA];
    __shared__ __align__(16) __nv_bfloat16 sAl[128*SA];
    __shared__ __align__(16) __nv_bfloat16 sBh[64*SA];
    __shared__ __align__(16) __nv_bfloat16 sBl[64*SA];

    const int K = E_DIM;
    int tid = threadIdx.x;
    int wid = tid >> 5, lid = tid & 31;
    int warpM = wid & 3, warpN = wid >> 2;
    long m0 = (long)blockIdx.y * 128, n0 = (long)blockIdx.x * 64;

    int gRow = lid >> 2;
    int cPair = (lid & 3) * 2;

    const int ap0 = tid, ap1 = tid + 256;
    const int ar0 = ap0 >> 2, aq0 = ap0 & 3;
    const int ar1 = ap1 >> 2, aq1 = ap1 & 3;
    const int br = tid >> 2, bq = tid & 3;

    float acc[2][4][4];
#pragma unroll
    for (int mt = 0; mt < 2; mt++)
#pragma unroll
        for (int nt = 0; nt < 4; nt++)
#pragma unroll
            for (int q = 0; q < 4; q++) acc[mt][nt][q] = 0.f;

    uint4 pah0 = *(const uint4*)&Ahi[(m0+ar0)*K + aq0*8];
    uint4 pah1 = *(const uint4*)&Ahi[(m0+ar1)*K + aq1*8];
    uint4 pal0 = *(const uint4*)&Alo[(m0+ar0)*K + aq0*8];
    uint4 pal1 = *(const uint4*)&Alo[(m0+ar1)*K + aq1*8];
    uint4 pbh  = *(const uint4*)&Bhi[(n0+br)*K + bq*8];
    uint4 pbl  = *(const uint4*)&Blo[(n0+br)*K + bq*8];

    for (int kc = 0; kc < K; kc += 32) {
        *(uint4*)&sAh[ar0*SA + aq0*8] = pah0;
        *(uint4*)&sAh[ar1*SA + aq1*8] = pah1;
        *(uint4*)&sAl[ar0*SA + aq0*8] = pal0;
        *(uint4*)&sAl[ar1*SA + aq1*8] = pal1;
        *(uint4*)&sBh[br*SA + bq*8] = pbh;
        *(uint4*)&sBl[br*SA + bq*8] = pbl;
        __syncthreads();

        if (kc + 32 < K) {
            int kn = kc + 32;
            pah0 = *(const uint4*)&Ahi[(m0+ar0)*K + kn + aq0*8];
            pah1 = *(const uint4*)&Ahi[(m0+ar1)*K + kn + aq1*8];
            pal0 = *(const uint4*)&Alo[(m0+ar0)*K + kn + aq0*8];
            pal1 = *(const uint4*)&Alo[(m0+ar1)*K + kn + aq1*8];
            pbh  = *(const uint4*)&Bhi[(n0+br)*K + kn + bq*8];
            pbl  = *(const uint4*)&Blo[(n0+br)*K + kn + bq*8];
        }

#pragma unroll
        for (int ks = 0; ks < 2; ks++) {
            int kb = ks * 16;
            uint32_t ah[2][4], al[2][4], bh[4][2], bl[4][2];
#pragma unroll
            for (int mt = 0; mt < 2; mt++) {
                int r = warpM*32 + mt*16 + gRow;
                ah[mt][0] = *(uint32_t*)&sAh[r*SA + kb + cPair];
                ah[mt][1] = *(uint32_t*)&sAh[(r+8)*SA + kb + cPair];
                ah[mt][2] = *(uint32_t*)&sAh[r*SA + kb + cPair + 8];
                ah[mt][3] = *(uint32_t*)&sAh[(r+8)*SA + kb + cPair + 8];
                al[mt][0] = *(uint32_t*)&sAl[r*SA + kb + cPair];
                al[mt][1] = *(uint32_t*)&sAl[(r+8)*SA + kb + cPair];
                al[mt][2] = *(uint32_t*)&sAl[r*SA + kb + cPair + 8];
                al[mt][3] = *(uint32_t*)&sAl[(r+8)*SA + kb + cPair + 8];
            }
#pragma unroll
            for (int nt = 0; nt < 4; nt++) {
                int n = warpN*32 + nt*8 + gRow;
                bh[nt][0] = *(uint32_t*)&sBh[n*SA + kb + cPair];
                bh[nt][1] = *(uint32_t*)&sBh[n*SA + kb + cPair + 8];
                bl[nt][0] = *(uint32_t*)&sBl[n*SA + kb + cPair];
                bl[nt][1] = *(uint32_t*)&sBl[n*SA + kb + cPair + 8];
            }
#pragma unroll
            for (int mt = 0; mt < 2; mt++)
#pragma unroll
                for (int nt = 0; nt < 4; nt++) {
                    mma16816(acc[mt][nt], ah[mt], bh[nt]);
                    mma16816(acc[mt][nt], ah[mt], bl[nt]);
                    mma16816(acc[mt][nt], al[mt], bh[nt]);
                }
        }
        __syncthreads();
    }

#pragma unroll
    for (int mt = 0; mt < 2; mt++) {
        long r0 = m0 + warpM*32 + mt*16 + gRow;
#pragma unroll
        for (int nt = 0; nt < 4; nt++) {
            long n = n0 + warpN*32 + nt*8 + cPair;
            float2 bia = *(const float2*)&bias[n];
            float2 o0 = { acc[mt][nt][0] + bia.x, acc[mt][nt][1] + bia.y };
            float2 o1 = { acc[mt][nt][2] + bia.x, acc[mt][nt][3] + bia.y };
            *(float2*)&C[r0*N_ + n] = o0;
            *(float2*)&C[(r0+8)*N_ + n] = o1;
        }
    }
}

// ================= HMMA flash attention with windowed bd =================
// delta = j - i:  <=0 : (q_i+rrb).rk[T-1+delta] ; ==1 : 0 ; >=2 : (q_{i+1}+rrb).rk[delta-2]
// Window slot w (per j-tile, base=j0-i0): rks[w] = R(base-63+w), w in [0,126]; w=127 zero.
// bd(ii,jj) = M[sel][jj-ii+63], sel = (delta<=0) ? ii : ii+1;  M[r][w] = qr_r . rks[w].
#define AST 72    // bf16 row stride (144B = 16 mod 128 -> conflict-free frag loads)
#define MST 132   // Ms fp32 row stride
#define O_QWH 0
#define O_QWL (O_QWH + 64*AST*2)
#define O_QRH (O_QWL + 64*AST*2)
#define O_QRL (O_QRH + 80*AST*2)
#define O_KTH (O_QRL + 80*AST*2)
#define O_KTL (O_KTH + 64*AST*2)
#define O_VTH (O_KTL + 64*AST*2)
#define O_VTL (O_VTH + 64*AST*2)
#define O_RKH (O_VTL + 64*AST*2)
#define O_RKL (O_RKH + 128*AST*2)
#define O_MS  (O_RKL + 128*AST*2)
#define O_MASK (O_MS + 80*MST*4)
#define ATTN_SMEM (O_MASK + 128)

__global__ __launch_bounds__(128, 1)
void attn_mma_kernel(const float* __restrict__ qkv, const float* __restrict__ rk,
                     const unsigned char* __restrict__ mask,
                     const float* __restrict__ rwb, const float* __restrict__ rrb,
                     __nv_bfloat16* __restrict__ ctx_hi, __nv_bfloat16* __restrict__ ctx_lo) {
    extern __shared__ char smem[];
    __nv_bfloat16* qwh = (__nv_bfloat16*)(smem + O_QWH);
    __nv_bfloat16* qwl = (__nv_bfloat16*)(smem + O_QWL);
    __nv_bfloat16* qrh = (__nv_bfloat16*)(smem + O_QRH);
    __nv_bfloat16* qrl = (__nv_bfloat16*)(smem + O_QRL);
    __nv_bfloat16* kth = (__nv_bfloat16*)(smem + O_KTH);
    __nv_bfloat16* ktl = (__nv_bfloat16*)(smem + O_KTL);
    __nv_bfloat16* vth = (__nv_bfloat16*)(smem + O_VTH);  // V^T: [d][j]
    __nv_bfloat16* vtl = (__nv_bfloat16*)(smem + O_VTL);
    __nv_bfloat16* rkh = (__nv_bfloat16*)(smem + O_RKH);
    __nv_bfloat16* rkl = (__nv_bfloat16*)(smem + O_RKL);
    float* Ms = (float*)(smem + O_MS);
    unsigned char* smask = (unsigned char*)(smem + O_MASK);

    int tid = threadIdx.x;
    int wid = tid >> 5, lid = tid & 31;
    int gRow = lid >> 2, cPair = (lid & 3) * 2;
    int i0 = blockIdx.x * 64, h = blockIdx.y, b = blockIdx.z;

    // ---- Q tiles: qw rows 0..63 (+rwb), qr rows 0..64 (+rrb), rows 65..79 zero ----
    for (int e = tid; e < 80*16; e += 128) {
        int ii = e >> 4, d4 = (e & 15) * 4;
        int t = i0 + ii;
        float4 qv = make_float4(0.f,0.f,0.f,0.f);
        bool ok = (ii <= 64) && (t < T_DIM);
        if (ok) qv = *(const float4*)&qkv[(long)(t*B_DIM + b)*E3 + h*D_DIM + d4];
        float4 wb = *(const float4*)&rwb[h*D_DIM + d4];
        float4 rb = *(const float4*)&rrb[h*D_DIM + d4];
        float qvv[4] = {qv.x, qv.y, qv.z, qv.w};
        float wbv[4] = {wb.x, wb.y, wb.z, wb.w};
        float rbv[4] = {rb.x, rb.y, rb.z, rb.w};
#pragma unroll
        for (int k = 0; k < 4; k++) {
            if (ii < 64) put_hl(qwh, qwl, ii*AST + d4 + k, qvv[k] + wbv[k]);
            float qrv = (ii <= 64) ? (qvv[k] + rbv[k]) : 0.f;
            put_hl(qrh, qrl, ii*AST + d4 + k, qrv);
        }
    }

    float out[8][4];
#pragma unroll
    for (int nt = 0; nt < 8; nt++)
#pragma unroll
        for (int q = 0; q < 4; q++) out[nt][q] = 0.f;
    float mrow[2] = { -1e30f, -1e30f };
    float lrow[2] = { 0.f, 0.f };

    const int iir0 = wid*16 + gRow;
    const float scale = 0.125f;

    for (int j0 = 0; j0 < T_DIM; j0 += 64) {
        __syncthreads();
        int base = j0 - i0;
        // K tile (row=j, k-contig) + V^T tile ([d][j])
        for (int e = tid; e < 64*16; e += 128) {
            int jj = e >> 4, d4 = (e & 15) * 4;
            long off = (long)((j0+jj)*B_DIM + b)*E3 + h*D_DIM + d4;
            float4 kv = *(const float4*)&qkv[off + E_DIM];
            float4 vv = *(const float4*)&qkv[off + 2*E_DIM];
            float kvv[4] = {kv.x, kv.y, kv.z, kv.w};
            float vvv[4] = {vv.x, vv.y, vv.z, vv.w};
#pragma unroll
            for (int k = 0; k < 4; k++) {
                put_hl(kth, ktl, jj*AST + d4 + k, kvv[k]);
                put_hl(vth, vtl, (d4+k)*AST + jj, vvv[k]);
            }
        }
        // rk window: [w][d], w 0..126 per R(delta); w=127 zeros
        for (int e = tid; e < 128*16; e += 128) {
            int w = e >> 4, d4 = (e & 15) * 4;
            float4 v = make_float4(0.f,0.f,0.f,0.f);
            if (w < 127) {
                int delta = base - 63 + w;
                if (delta <= 0)      v = *(const float4*)&rk[(long)(T_DIM-1+delta)*E_DIM + h*D_DIM + d4];
                else if (delta >= 2) v = *(const float4*)&rk[(long)(delta-2)*E_DIM + h*D_DIM + d4];
            }
            float vv4[4] = {v.x, v.y, v.z, v.w};
#pragma unroll
            for (int k = 0; k < 4; k++)
                put_hl(rkh, rkl, w*AST + d4 + k, vv4[k]);
        }
        if (tid < 64) smask[tid] = mask[b*T_DIM + j0 + tid];
        __syncthreads();

        // ---- ac: per warp 16i x 64j, 3-product hi/lo ----
        float sc[8][4];
#pragma unroll
        for (int nt = 0; nt < 8; nt++)
#pragma unroll
            for (int q = 0; q < 4; q++) sc[nt][q] = 0.f;
#pragma unroll
        for (int ks = 0; ks < 4; ks++) {
            int kb = ks*16;
            uint32_t ah[4], al[4];
            ah[0] = *(uint32_t*)&qwh[iir0*AST + kb + cPair];
            ah[1] = *(uint32_t*)&qwh[(iir0+8)*AST + kb + cPair];
            ah[2] = *(uint32_t*)&qwh[iir0*AST + kb + cPair + 8];
            ah[3] = *(uint32_t*)&qwh[(iir0+8)*AST + kb + cPair + 8];
            al[0] = *(uint32_t*)&qwl[iir0*AST + kb + cPair];
            al[1] = *(uint32_t*)&qwl[(iir0+8)*AST + kb + cPair];
            al[2] = *(uint32_t*)&qwl[iir0*AST + kb + cPair + 8];
            al[3] = *(uint32_t*)&qwl[(iir0+8)*AST + kb + cPair + 8];
#pragma unroll
            for (int nt = 0; nt < 8; nt++) {
                int nr = nt*8 + gRow;
                uint32_t bh[2], bl[2];
                bh[0] = *(uint32_t*)&kth[nr*AST + kb + cPair];
                bh[1] = *(uint32_t*)&kth[nr*AST + kb + cPair + 8];
                bl[0] = *(uint32_t*)&ktl[nr*AST + kb + cPair];
                bl[1] = *(uint32_t*)&ktl[nr*AST + kb + cPair + 8];
                mma16816(sc[nt], ah, bh);
                mma16816(sc[nt], ah, bl);
                mma16816(sc[nt], al, bh);
            }
        }

        // ---- M = qr (80 rows) x rks^T (this warp: 32-wide w strip) ----
        {
            int ws = wid * 32;
#pragma unroll
            for (int mt = 0; mt < 5; mt++) {
                float cm[4][4];
#pragma unroll
                for (int nt = 0; nt < 4; nt++)
#pragma unroll
                    for (int q = 0; q < 4; q++) cm[nt][q] = 0.f;
                int ar = mt*16 + gRow;
#pragma unroll
                for (int ks = 0; ks < 4; ks++) {
                    int kb = ks*16;
                    uint32_t ah[4], al[4];
                    ah[0] = *(uint32_t*)&qrh[ar*AST + kb + cPair];
                    ah[1] = *(uint32_t*)&qrh[(ar+8)*AST + kb + cPair];
                    ah[2] = *(uint32_t*)&qrh[ar*AST + kb + cPair + 8];
                    ah[3] = *(uint32_t*)&qrh[(ar+8)*AST + kb + cPair + 8];
                    al[0] = *(uint32_t*)&qrl[ar*AST + kb + cPair];
                    al[1] = *(uint32_t*)&qrl[(ar+8)*AST + kb + cPair];
                    al[2] = *(uint32_t*)&qrl[ar*AST + kb + cPair + 8];
                    al[3] = *(uint32_t*)&qrl[(ar+8)*AST + kb + cPair + 8];
#pragma unroll
                    for (int nt = 0; nt < 4; nt++) {
                        int nr = ws + nt*8 + gRow;
                        uint32_t bh[2], bl[2];
                        bh[0] = *(uint32_t*)&rkh[nr*AST + kb + cPair];
                        bh[1] = *(uint32_t*)&rkh[nr*AST + kb + cPair + 8];
                        bl[0] = *(uint32_t*)&rkl[nr*AST + kb + cPair];
                        bl[1] = *(uint32_t*)&rkl[nr*AST + kb + cPair + 8];
                        mma16816(cm[nt], ah, bh);
                        mma16816(cm[nt], ah, bl);
                        mma16816(cm[nt], al, bh);
                    }
                }
#pragma unroll
                for (int nt = 0; nt < 4; nt++) {
                    int wc = ws + nt*8 + cPair;
                    *(float2*)&Ms[(mt*16+gRow)*MST + wc]   = make_float2(cm[nt][0], cm[nt][1]);
                    *(float2*)&Ms[(mt*16+gRow+8)*MST + wc] = make_float2(cm[nt][2], cm[nt][3]);
                }
            }
        }
        __syncthreads();

        // ---- gather bd + scale + mask ----
#pragma unroll
        for (int nt = 0; nt < 8; nt++) {
#pragma unroll
            for (int q = 0; q < 4; q++) {
                int ii = iir0 + ((q >> 1) << 3);
                int jj = nt*8 + cPair + (q & 1);
                int delta = base + jj - ii;
                int w = jj - ii + 63;
                int sel = (delta <= 0) ? ii : (ii + 1);
                float s = (sc[nt][q] + Ms[sel*MST + w]) * scale;
                if (smask[jj]) s = -1e9f;
                sc[nt][q] = s;
            }
        }

        // ---- online softmax (rows: q{0,1} -> row gRow; q{2,3} -> gRow+8) ----
#pragma unroll
        for (int rr = 0; rr < 2; rr++) {
            float mx = -1e30f;
#pragma unroll
            for (int nt = 0; nt < 8; nt++)
                mx = fmaxf(mx, fmaxf(sc[nt][2*rr], sc[nt][2*rr+1]));
            mx = fmaxf(mx, __shfl_xor_sync(0xffffffffu, mx, 1));
            mx = fmaxf(mx, __shfl_xor_sync(0xffffffffu, mx, 2));
            float mnew = fmaxf(mrow[rr], mx);
            float corr = __expf(mrow[rr] - mnew);
            float rs = 0.f;
#pragma unroll
            for (int nt = 0; nt < 8; nt++) {
                float p0 = __expf(sc[nt][2*rr]   - mnew);
                float p1 = __expf(sc[nt][2*rr+1] - mnew);
                sc[nt][2*rr] = p0; sc[nt][2*rr+1] = p1;
                rs += p0 + p1;
            }
            rs += __shfl_xor_sync(0xffffffffu, rs, 1);
            rs += __shfl_xor_sync(0xffffffffu, rs, 2);
            lrow[rr] = lrow[rr]*corr + rs;
            mrow[rr] = mnew;
#pragma unroll
            for (int nt = 0; nt < 8; nt++) {
                out[nt][2*rr]   *= corr;
                out[nt][2*rr+1] *= corr;
            }
        }

        // ---- PV: P (in-register a-frags, hi/lo) x V^T (smem b-frags, hi/lo) ----
#pragma unroll
        for (int ks = 0; ks < 4; ks++) {
            int t0 = 2*ks, t1 = 2*ks + 1;
            uint32_t pah[4], pal[4];
            split2(sc[t0][0], sc[t0][1], pah[0], pal[0]);
            split2(sc[t0][2], sc[t0][3], pah[1], pal[1]);
            split2(sc[t1][0], sc[t1][1], pah[2], pal[2]);
            split2(sc[t1][2], sc[t1][3], pah[3], pal[3]);
            int kb = ks*16;
#pragma unroll
            for (int nt = 0; nt < 8; nt++) {
                int nr = nt*8 + gRow;
                uint32_t bh[2], bl[2];
                bh[0] = *(uint32_t*)&vth[nr*AST + kb + cPair];
                bh[1] = *(uint32_t*)&vth[nr*AST + kb + cPair + 8];
                bl[0] = *(uint32_t*)&vtl[nr*AST + kb + cPair];
                bl[1] = *(uint32_t*)&vtl[nr*AST + kb + cPair + 8];
                mma16816(out[nt], pah, bh);
                mma16816(out[nt], pah, bl);
                mma16816(out[nt], pal, bh);
            }
        }
    }

    // ---- epilogue: normalize, split hi/lo, store ----
    float inv0 = 1.f / lrow[0], inv1 = 1.f / lrow[1];
    int t0 = i0 + iir0, t1 = t0 + 8;
#pragma unroll
    for (int nt = 0; nt < 8; nt++) {
        long o0 = (long)(t0*B_DIM + b)*E_DIM + h*D_DIM + nt*8 + cPair;
        long o1 = (long)(t1*B_DIM + b)*E_DIM + h*D_DIM + nt*8 + cPair;
        uint32_t hi, lo;
        split2(out[nt][0]*inv0, out[nt][1]*inv0, hi, lo);
        *(uint32_t*)&ctx_hi[o0] = hi; *(uint32_t*)&ctx_lo[o0] = lo;
        split2(out[nt][2]*inv1, out[nt][3]*inv1, hi, lo);
        *(uint32_t*)&ctx_hi[o1] = hi; *(uint32_t*)&ctx_lo[o1] = lo;
    }
}

extern "C" void kernel_launch(void* const* d_in, const int* in_sizes, int n_in,
                              void* d_out, int out_size) {
    const float* input   = (const float*)d_in[0];
    const float* pos     = (const float*)d_in[1];
    const int*   indices = (const int*)  d_in[2];
    const unsigned char* mask = (const unsigned char*)d_in[3];
    const float* in_w  = (const float*)d_in[4];
    const float* pos_w = (const float*)d_in[5];
    const float* out_w = (const float*)d_in[6];
    const float* in_b  = (const float*)d_in[7];
    const float* pos_b = (const float*)d_in[8];
    const float* out_b = (const float*)d_in[9];
    const float* r_i = (const float*)d_in[10];
    const float* s_i = (const float*)d_in[11];
    const float* r_p = (const float*)d_in[12];
    const float* s_p = (const float*)d_in[13];
    const float* r_o = (const float*)d_in[14];
    const float* s_o = (const float*)d_in[15];
    const float* rwb = (const float*)d_in[16];
    const float* rrb = (const float*)d_in[17];
    float* out = (float*)d_out;

    float *qkv, *rk;
    __nv_bfloat16 *in_hi, *in_lo, *pos_hi, *pos_lo, *ctx_hi, *ctx_lo;
    __nv_bfloat16 *win_hi, *win_lo, *wpos_hi, *wpos_lo, *wout_hi, *wout_lo;
    cudaGetSymbolAddress((void**)&qkv,   g_qkv);
    cudaGetSymbolAddress((void**)&rk,    g_rk);
    cudaGetSymbolAddress((void**)&in_hi, g_in_hi);
    cudaGetSymbolAddress((void**)&in_lo, g_in_lo);
    cudaGetSymbolAddress((void**)&pos_hi,g_pos_hi);
    cudaGetSymbolAddress((void**)&pos_lo,g_pos_lo);
    cudaGetSymbolAddress((void**)&ctx_hi,g_ctx_hi);
    cudaGetSymbolAddress((void**)&ctx_lo,g_ctx_lo);
    cudaGetSymbolAddress((void**)&win_hi,g_win_hi);
    cudaGetSymbolAddress((void**)&win_lo,g_win_lo);
    cudaGetSymbolAddress((void**)&wpos_hi,g_wpos_hi);
    cudaGetSymbolAddress((void**)&wpos_lo,g_wpos_lo);
    cudaGetSymbolAddress((void**)&wout_hi,g_wout_hi);
    cudaGetSymbolAddress((void**)&wout_lo,g_wout_lo);

    const int thr = 256;
    build_w_bf16<<<(E3*(E_DIM/8) + thr-1)/thr, thr>>>(in_w,  r_i, s_i, indices, win_hi,  win_lo,  E3);
    build_w_bf16<<<(E_DIM*(E_DIM/8) + thr-1)/thr, thr>>>(pos_w, r_p, s_p, indices, wpos_hi, wpos_lo, E_DIM);
    build_w_bf16<<<(E_DIM*(E_DIM/8) + thr-1)/thr, thr>>>(out_w, r_o, s_o, indices, wout_hi, wout_lo, E_DIM);
    conv_bf16<<<(T_DIM*B_DIM*E_DIM/4 + thr-1)/thr, thr>>>(input, in_hi, in_lo, T_DIM*B_DIM*E_DIM);
    conv_bf16<<<(T_DIM*E_DIM/4 + thr-1)/thr, thr>>>(pos, pos_hi, pos_lo, T_DIM*E_DIM);

    gemm_mma<<<dim3(E3/64, (T_DIM*B_DIM)/128), 256>>>(in_hi, in_lo, win_hi, win_lo, in_b, qkv, E3);
    gemm_mma<<<dim3(E_DIM/64, T_DIM/128), 256>>>(pos_hi, pos_lo, wpos_hi, wpos_lo, pos_b, rk, E_DIM);

    cudaFuncSetAttribute(attn_mma_kernel, cudaFuncAttributeMaxDynamicSharedMemorySize, ATTN_SMEM);
    attn_mma_kernel<<<dim3(T_DIM/64, H_DIM, B_DIM), 128, ATTN_SMEM>>>(qkv, rk, mask, rwb, rrb, ctx_hi, ctx_lo);

    gemm_mma<<<dim3(E_DIM/64, (T_DIM*B_DIM)/128), 256>>>(ctx_hi, ctx_lo, wout_hi, wout_lo, out_b, out, E_DIM);
}

// round 14
// speedup vs baseline: 1.4557x; 1.3946x over previous
#include <cuda_runtime.h>
#include <cuda_bf16.h>
#include <math.h>
#include <stdint.h>

#define T_DIM 1024
#define B_DIM 4
#define E_DIM 1024
#define H_DIM 16
#define D_DIM 64
#define RANK_ 4
#define E3 (3*E_DIM)
#define NP (B_DIM*H_DIM)   // 64 (b,h) pairs; p = h*B + b

// ---- device scratch ----
__device__ float g_qkv  [T_DIM*B_DIM*E3];
__device__ float g_rk   [T_DIM*E_DIM];
__device__ float g_G    [(long)NP*T_DIM*T_DIM];   // bd source: G[p][t][r]

__device__ __align__(16) __nv_bfloat16 g_in_hi [T_DIM*B_DIM*E_DIM];
__device__ __align__(16) __nv_bfloat16 g_in_lo [T_DIM*B_DIM*E_DIM];
__device__ __align__(16) __nv_bfloat16 g_pos_hi[T_DIM*E_DIM];
__device__ __align__(16) __nv_bfloat16 g_pos_lo[T_DIM*E_DIM];
__device__ __align__(16) __nv_bfloat16 g_ctx_hi[T_DIM*B_DIM*E_DIM];
__device__ __align__(16) __nv_bfloat16 g_ctx_lo[T_DIM*B_DIM*E_DIM];
__device__ __align__(16) __nv_bfloat16 g_win_hi [E3*E_DIM];
__device__ __align__(16) __nv_bfloat16 g_win_lo [E3*E_DIM];
__device__ __align__(16) __nv_bfloat16 g_wpos_hi[E_DIM*E_DIM];
__device__ __align__(16) __nv_bfloat16 g_wpos_lo[E_DIM*E_DIM];
__device__ __align__(16) __nv_bfloat16 g_wout_hi[E_DIM*E_DIM];
__device__ __align__(16) __nv_bfloat16 g_wout_lo[E_DIM*E_DIM];
// packs: [p][t][64] (p = h*B+b)
__device__ __align__(16) __nv_bfloat16 g_qw_hi[NP*T_DIM*D_DIM];
__device__ __align__(16) __nv_bfloat16 g_qw_lo[NP*T_DIM*D_DIM];
__device__ __align__(16) __nv_bfloat16 g_qr_hi[NP*T_DIM*D_DIM];
__device__ __align__(16) __nv_bfloat16 g_qr_lo[NP*T_DIM*D_DIM];
__device__ __align__(16) __nv_bfloat16 g_k_hi [NP*T_DIM*D_DIM];
__device__ __align__(16) __nv_bfloat16 g_k_lo [NP*T_DIM*D_DIM];
// V transposed: [p][d][t]
__device__ __align__(16) __nv_bfloat16 g_vt_hi[NP*D_DIM*T_DIM];
__device__ __align__(16) __nv_bfloat16 g_vt_lo[NP*D_DIM*T_DIM];
// rk packed per head: [h][t][64]
__device__ __align__(16) __nv_bfloat16 g_rkp_hi[H_DIM*T_DIM*D_DIM];
__device__ __align__(16) __nv_bfloat16 g_rkp_lo[H_DIM*T_DIM*D_DIM];

// ---- warp-level bf16 MMA ----
__device__ __forceinline__ void mma16816(float* c, const uint32_t* a, const uint32_t* b){
    asm volatile(
        "mma.sync.aligned.m16n8k16.row.col.f32.bf16.bf16.f32 "
        "{%0,%1,%2,%3}, {%4,%5,%6,%7}, {%8,%9}, {%0,%1,%2,%3};"
        : "+f"(c[0]), "+f"(c[1]), "+f"(c[2]), "+f"(c[3])
        : "r"(a[0]), "r"(a[1]), "r"(a[2]), "r"(a[3]), "r"(b[0]), "r"(b[1]));
}

__device__ __forceinline__ void split2(float a, float b, uint32_t& hi, uint32_t& lo){
    __nv_bfloat16 ah = __float2bfloat16(a), bh = __float2bfloat16(b);
    __nv_bfloat16 al = __float2bfloat16(a - __bfloat162float(ah));
    __nv_bfloat16 bl = __float2bfloat16(b - __bfloat162float(bh));
    __nv_bfloat162 H; H.x = ah; H.y = bh;
    __nv_bfloat162 L; L.x = al; L.y = bl;
    hi = *(uint32_t*)&H; lo = *(uint32_t*)&L;
}
__device__ __forceinline__ void put_hl(__nv_bfloat16* ph, __nv_bfloat16* pl, long idx, float v){
    __nv_bfloat16 h = __float2bfloat16(v);
    ph[idx] = h;
    pl[idx] = __float2bfloat16(v - __bfloat162float(h));
}

// ---- W' = W + sum_r outer(r,s); TRANSPOSED [f][e] bf16 hi/lo ----
__global__ void build_w_bf16(const float* __restrict__ base, const float* __restrict__ rfac,
                             const float* __restrict__ sfac, const int* __restrict__ idx,
                             __nv_bfloat16* __restrict__ whi, __nv_bfloat16* __restrict__ wlo,
                             int F) {
    int lang = idx[0];
    long i = (long)blockIdx.x * blockDim.x + threadIdx.x;
    long total = (long)F * (E_DIM/8);
    if (i >= total) return;
    int f = (int)(i % F);
    int e0 = (int)(i / F) * 8;
    const float* rp = rfac + (long)lang * RANK_ * E_DIM;
    const float* sp = sfac + (long)lang * RANK_ * F;
    float sv[RANK_];
#pragma unroll
    for (int r = 0; r < RANK_; r++) sv[r] = sp[(long)r*F + f];
    __nv_bfloat16 h8[8], l8[8];
#pragma unroll
    for (int j = 0; j < 8; j++) {
        int e = e0 + j;
        float v = base[(long)e*F + f];
#pragma unroll
        for (int r = 0; r < RANK_; r++) v = fmaf(rp[r*E_DIM + e], sv[r], v);
        __nv_bfloat16 h = __float2bfloat16(v);
        h8[j] = h;
        l8[j] = __float2bfloat16(v - __bfloat162float(h));
    }
    *(uint4*)&whi[(long)f*E_DIM + e0] = *(uint4*)h8;
    *(uint4*)&wlo[(long)f*E_DIM + e0] = *(uint4*)l8;
}

// ---- fp32 -> bf16 hi/lo ----
__global__ void conv_bf16(const float* __restrict__ x, __nv_bfloat16* __restrict__ hi,
                          __nv_bfloat16* __restrict__ lo, int n) {
    int i = (blockIdx.x*blockDim.x + threadIdx.x) * 4;
    if (i >= n) return;
    float4 v = *(const float4*)&x[i];
    float vv[4] = {v.x, v.y, v.z, v.w};
    __nv_bfloat16 h4[4], l4[4];
#pragma unroll
    for (int j = 0; j < 4; j++) {
        __nv_bfloat16 h = __float2bfloat16(vv[j]);
        h4[j] = h;
        l4[j] = __float2bfloat16(vv[j] - __bfloat162float(h));
    }
    *(uint2*)&hi[i] = *(uint2*)h4;
    *(uint2*)&lo[i] = *(uint2*)l4;
}

// ---- HMMA bf16-split GEMM: C[M,N] = A[M,K] @ B[N,K]^T + bias (passing) ----
#define SA 56

__global__ __launch_bounds__(256, 2)
void gemm_mma(const __nv_bfloat16* __restrict__ Ahi, const __nv_bfloat16* __restrict__ Alo,
              const __nv_bfloat16* __restrict__ Bhi, const __nv_bfloat16* __restrict__ Blo,
              const float* __restrict__ bias, float* __restrict__ C, int N_) {
    __shared__ __align__(16) __nv_bfloat16 sAh[128*SA];
    __shared__ __align__(16) __nv_bfloat16 sAl[128*SA];
    __shared__ __align__(16) __nv_bfloat16 sBh[64*SA];
    __shared__ __align__(16) __nv_bfloat16 sBl[64*SA];

    const int K = E_DIM;
    int tid = threadIdx.x;
    int wid = tid >> 5, lid = tid & 31;
    int warpM = wid & 3, warpN = wid >> 2;
    long m0 = (long)blockIdx.y * 128, n0 = (long)blockIdx.x * 64;
    int gRow = lid >> 2;
    int cPair = (lid & 3) * 2;
    const int ap0 = tid, ap1 = tid + 256;
    const int ar0 = ap0 >> 2, aq0 = ap0 & 3;
    const int ar1 = ap1 >> 2, aq1 = ap1 & 3;
    const int br = tid >> 2, bq = tid & 3;

    float acc[2][4][4];
#pragma unroll
    for (int mt = 0; mt < 2; mt++)
#pragma unroll
        for (int nt = 0; nt < 4; nt++)
#pragma unroll
            for (int q = 0; q < 4; q++) acc[mt][nt][q] = 0.f;

    uint4 pah0 = *(const uint4*)&Ahi[(m0+ar0)*K + aq0*8];
    uint4 pah1 = *(const uint4*)&Ahi[(m0+ar1)*K + aq1*8];
    uint4 pal0 = *(const uint4*)&Alo[(m0+ar0)*K + aq0*8];
    uint4 pal1 = *(const uint4*)&Alo[(m0+ar1)*K + aq1*8];
    uint4 pbh  = *(const uint4*)&Bhi[(n0+br)*K + bq*8];
    uint4 pbl  = *(const uint4*)&Blo[(n0+br)*K + bq*8];

    for (int kc = 0; kc < K; kc += 32) {
        *(uint4*)&sAh[ar0*SA + aq0*8] = pah0;
        *(uint4*)&sAh[ar1*SA + aq1*8] = pah1;
        *(uint4*)&sAl[ar0*SA + aq0*8] = pal0;
        *(uint4*)&sAl[ar1*SA + aq1*8] = pal1;
        *(uint4*)&sBh[br*SA + bq*8] = pbh;
        *(uint4*)&sBl[br*SA + bq*8] = pbl;
        __syncthreads();
        if (kc + 32 < K) {
            int kn = kc + 32;
            pah0 = *(const uint4*)&Ahi[(m0+ar0)*K + kn + aq0*8];
            pah1 = *(const uint4*)&Ahi[(m0+ar1)*K + kn + aq1*8];
            pal0 = *(const uint4*)&Alo[(m0+ar0)*K + kn + aq0*8];
            pal1 = *(const uint4*)&Alo[(m0+ar1)*K + kn + aq1*8];
            pbh  = *(const uint4*)&Bhi[(n0+br)*K + kn + bq*8];
            pbl  = *(const uint4*)&Blo[(n0+br)*K + kn + bq*8];
        }
#pragma unroll
        for (int ks = 0; ks < 2; ks++) {
            int kb = ks * 16;
            uint32_t ah[2][4], al[2][4], bh[4][2], bl[4][2];
#pragma unroll
            for (int mt = 0; mt < 2; mt++) {
                int r = warpM*32 + mt*16 + gRow;
                ah[mt][0] = *(uint32_t*)&sAh[r*SA + kb + cPair];
                ah[mt][1] = *(uint32_t*)&sAh[(r+8)*SA + kb + cPair];
                ah[mt][2] = *(uint32_t*)&sAh[r*SA + kb + cPair + 8];
                ah[mt][3] = *(uint32_t*)&sAh[(r+8)*SA + kb + cPair + 8];
                al[mt][0] = *(uint32_t*)&sAl[r*SA + kb + cPair];
                al[mt][1] = *(uint32_t*)&sAl[(r+8)*SA + kb + cPair];
                al[mt][2] = *(uint32_t*)&sAl[r*SA + kb + cPair + 8];
                al[mt][3] = *(uint32_t*)&sAl[(r+8)*SA + kb + cPair + 8];
            }
#pragma unroll
            for (int nt = 0; nt < 4; nt++) {
                int n = warpN*32 + nt*8 + gRow;
                bh[nt][0] = *(uint32_t*)&sBh[n*SA + kb + cPair];
                bh[nt][1] = *(uint32_t*)&sBh[n*SA + kb + cPair + 8];
                bl[nt][0] = *(uint32_t*)&sBl[n*SA + kb + cPair];
                bl[nt][1] = *(uint32_t*)&sBl[n*SA + kb + cPair + 8];
            }
#pragma unroll
            for (int mt = 0; mt < 2; mt++)
#pragma unroll
                for (int nt = 0; nt < 4; nt++) {
                    mma16816(acc[mt][nt], ah[mt], bh[nt]);
                    mma16816(acc[mt][nt], ah[mt], bl[nt]);
                    mma16816(acc[mt][nt], al[mt], bh[nt]);
                }
        }
        __syncthreads();
    }
#pragma unroll
    for (int mt = 0; mt < 2; mt++) {
        long r0 = m0 + warpM*32 + mt*16 + gRow;
#pragma unroll
        for (int nt = 0; nt < 4; nt++) {
            long n = n0 + warpN*32 + nt*8 + cPair;
            float2 bia = *(const float2*)&bias[n];
            float2 o0 = { acc[mt][nt][0] + bia.x, acc[mt][nt][1] + bia.y };
            float2 o1 = { acc[mt][nt][2] + bia.x, acc[mt][nt][3] + bia.y };
            *(float2*)&C[r0*N_ + n] = o0;
            *(float2*)&C[(r0+8)*N_ + n] = o1;
        }
    }
}

// ---- prep: qkv -> qw/qr/k packs [p][t][64] bf16 hi/lo ----
__global__ void prep_qkv(const float* __restrict__ qkv,
                         const float* __restrict__ rwb, const float* __restrict__ rrb) {
    long gid = (long)blockIdx.x * blockDim.x + threadIdx.x;
    if (gid >= (long)NP*T_DIM*16) return;
    int d4 = (int)(gid & 15) * 4;
    int t  = (int)(gid >> 4) & (T_DIM-1);
    int p  = (int)(gid >> 14);
    int h = p >> 2, b = p & 3;
    long src = (long)(t*B_DIM + b)*E3 + h*D_DIM + d4;
    float4 qv = *(const float4*)&qkv[src];
    float4 kv = *(const float4*)&qkv[src + E_DIM];
    float4 wb = *(const float4*)&rwb[h*D_DIM + d4];
    float4 rb = *(const float4*)&rrb[h*D_DIM + d4];
    long dst = (long)p*T_DIM*D_DIM + (long)t*D_DIM + d4;
    float qvv[4] = {qv.x,qv.y,qv.z,qv.w};
    float kvv[4] = {kv.x,kv.y,kv.z,kv.w};
    float wbv[4] = {wb.x,wb.y,wb.z,wb.w};
    float rbv[4] = {rb.x,rb.y,rb.z,rb.w};
    __nv_bfloat16 a_h[4], a_l[4], r_h[4], r_l[4], k_h[4], k_l[4];
#pragma unroll
    for (int k = 0; k < 4; k++) {
        float a = qvv[k] + wbv[k];
        __nv_bfloat16 hh = __float2bfloat16(a);
        a_h[k] = hh; a_l[k] = __float2bfloat16(a - __bfloat162float(hh));
        float r = qvv[k] + rbv[k];
        hh = __float2bfloat16(r);
        r_h[k] = hh; r_l[k] = __float2bfloat16(r - __bfloat162float(hh));
        hh = __float2bfloat16(kvv[k]);
        k_h[k] = hh; k_l[k] = __float2bfloat16(kvv[k] - __bfloat162float(hh));
    }
    *(uint2*)&g_qw_hi[dst] = *(uint2*)a_h;  *(uint2*)&g_qw_lo[dst] = *(uint2*)a_l;
    *(uint2*)&g_qr_hi[dst] = *(uint2*)r_h;  *(uint2*)&g_qr_lo[dst] = *(uint2*)r_l;
    *(uint2*)&g_k_hi [dst] = *(uint2*)k_h;  *(uint2*)&g_k_lo [dst] = *(uint2*)k_l;
}

// ---- prep: V (from qkv) -> transposed packs [p][d][t] via smem tile ----
__global__ void prep_v(const float* __restrict__ qkv) {
    __shared__ __nv_bfloat16 svh[64*68], svl[64*68];
    int tid = threadIdx.x;
    int t0 = blockIdx.x * 64;
    int p = blockIdx.y;
    int h = p >> 2, b = p & 3;
    for (int e = tid; e < 1024; e += 256) {
        int tt = e >> 4, d4 = (e & 15) * 4;
        long src = (long)((t0+tt)*B_DIM + b)*E3 + 2*E_DIM + h*D_DIM + d4;
        float4 v = *(const float4*)&qkv[src];
        float vv[4] = {v.x,v.y,v.z,v.w};
#pragma unroll
        for (int k = 0; k < 4; k++)
            put_hl(svh, svl, tt*68 + d4 + k, vv[k]);
    }
    __syncthreads();
    // write rows d: 4 consecutive t per uint2
    for (int e = tid; e < 1024; e += 256) {
        int d = e >> 4, t4 = (e & 15) * 4;
        __nv_bfloat16 oh[4], ol[4];
#pragma unroll
        for (int k = 0; k < 4; k++) {
            oh[k] = svh[(t4+k)*68 + d];
            ol[k] = svl[(t4+k)*68 + d];
        }
        long dst = (long)p*D_DIM*T_DIM + (long)d*T_DIM + t0 + t4;
        *(uint2*)&g_vt_hi[dst] = *(uint2*)oh;
        *(uint2*)&g_vt_lo[dst] = *(uint2*)ol;
    }
}

// ---- prep: rk -> [h][t][64] packs ----
__global__ void prep_rk(const float* __restrict__ rk) {
    long gid = (long)blockIdx.x * blockDim.x + threadIdx.x;
    if (gid >= (long)H_DIM*T_DIM*16) return;
    int d4 = (int)(gid & 15) * 4;
    int t  = (int)(gid >> 4) & (T_DIM-1);
    int h  = (int)(gid >> 14);
    float4 v = *(const float4*)&rk[(long)t*E_DIM + h*D_DIM + d4];
    float vv[4] = {v.x,v.y,v.z,v.w};
    long dst = (long)h*T_DIM*D_DIM + (long)t*D_DIM + d4;
    __nv_bfloat16 oh[4], ol[4];
#pragma unroll
    for (int k = 0; k < 4; k++) {
        __nv_bfloat16 hh = __float2bfloat16(vv[k]);
        oh[k] = hh; ol[k] = __float2bfloat16(vv[k] - __bfloat162float(hh));
    }
    *(uint2*)&g_rkp_hi[dst] = *(uint2*)oh;
    *(uint2*)&g_rkp_lo[dst] = *(uint2*)ol;
}

// ---- G GEMM: G[p] = qr_pack[p] (1024x64) @ rkp[h]^T (1024x64)^T, fp32, batched ----
#define GSA 72
#define GG_SMEM ((128*GSA + 64*GSA) * 2 * 2)

__global__ __launch_bounds__(256, 2)
void gemm_g() {
    extern __shared__ __nv_bfloat16 gsm[];
    __nv_bfloat16* sAh = gsm;
    __nv_bfloat16* sAl = sAh + 128*GSA;
    __nv_bfloat16* sBh = sAl + 128*GSA;
    __nv_bfloat16* sBl = sBh + 64*GSA;

    int tid = threadIdx.x;
    int wid = tid >> 5, lid = tid & 31;
    int warpM = wid & 3, warpN = wid >> 2;
    int gRow = lid >> 2, cPair = (lid & 3) * 2;
    int p = blockIdx.z;
    long m0 = (long)blockIdx.y * 128, n0 = (long)blockIdx.x * 64;
    const __nv_bfloat16* Ah = g_qr_hi + (long)p*T_DIM*D_DIM;
    const __nv_bfloat16* Al = g_qr_lo + (long)p*T_DIM*D_DIM;
    const __nv_bfloat16* Bh = g_rkp_hi + (long)(p >> 2)*T_DIM*D_DIM;
    const __nv_bfloat16* Bl = g_rkp_lo + (long)(p >> 2)*T_DIM*D_DIM;
    float* C = g_G + (long)p*T_DIM*T_DIM;

    for (int e = tid; e < 1024; e += 256) {
        int r = e >> 3, q = e & 7;
        *(uint4*)&sAh[r*GSA + q*8] = *(const uint4*)&Ah[(m0+r)*D_DIM + q*8];
        *(uint4*)&sAl[r*GSA + q*8] = *(const uint4*)&Al[(m0+r)*D_DIM + q*8];
    }
    for (int e = tid; e < 512; e += 256) {
        int r = e >> 3, q = e & 7;
        *(uint4*)&sBh[r*GSA + q*8] = *(const uint4*)&Bh[(n0+r)*D_DIM + q*8];
        *(uint4*)&sBl[r*GSA + q*8] = *(const uint4*)&Bl[(n0+r)*D_DIM + q*8];
    }
    __syncthreads();

    float acc[2][4][4];
#pragma unroll
    for (int mt = 0; mt < 2; mt++)
#pragma unroll
        for (int nt = 0; nt < 4; nt++)
#pragma unroll
            for (int q = 0; q < 4; q++) acc[mt][nt][q] = 0.f;

#pragma unroll
    for (int ks = 0; ks < 4; ks++) {
        int kb = ks * 16;
        uint32_t ah[2][4], al[2][4], bh[4][2], bl[4][2];
#pragma unroll
        for (int mt = 0; mt < 2; mt++) {
            int r = warpM*32 + mt*16 + gRow;
            ah[mt][0] = *(uint32_t*)&sAh[r*GSA + kb + cPair];
            ah[mt][1] = *(uint32_t*)&sAh[(r+8)*GSA + kb + cPair];
            ah[mt][2] = *(uint32_t*)&sAh[r*GSA + kb + cPair + 8];
            ah[mt][3] = *(uint32_t*)&sAh[(r+8)*GSA + kb + cPair + 8];
            al[mt][0] = *(uint32_t*)&sAl[r*GSA + kb + cPair];
            al[mt][1] = *(uint32_t*)&sAl[(r+8)*GSA + kb + cPair];
            al[mt][2] = *(uint32_t*)&sAl[r*GSA + kb + cPair + 8];
            al[mt][3] = *(uint32_t*)&sAl[(r+8)*GSA + kb + cPair + 8];
        }
#pragma unroll
        for (int nt = 0; nt < 4; nt++) {
            int n = warpN*32 + nt*8 + gRow;
            bh[nt][0] = *(uint32_t*)&sBh[n*GSA + kb + cPair];
            bh[nt][1] = *(uint32_t*)&sBh[n*GSA + kb + cPair + 8];
            bl[nt][0] = *(uint32_t*)&sBl[n*GSA + kb + cPair];
            bl[nt][1] = *(uint32_t*)&sBl[n*GSA + kb + cPair + 8];
        }
#pragma unroll
        for (int mt = 0; mt < 2; mt++)
#pragma unroll
            for (int nt = 0; nt < 4; nt++) {
                mma16816(acc[mt][nt], ah[mt], bh[nt]);
                mma16816(acc[mt][nt], ah[mt], bl[nt]);
                mma16816(acc[mt][nt], al[mt], bh[nt]);
            }
    }
#pragma unroll
    for (int mt = 0; mt < 2; mt++) {
        long r0 = m0 + warpM*32 + mt*16 + gRow;
#pragma unroll
        for (int nt = 0; nt < 4; nt++) {
            long n = n0 + warpN*32 + nt*8 + cPair;
            *(float2*)&C[r0*T_DIM + n] = make_float2(acc[mt][nt][0], acc[mt][nt][1]);
            *(float2*)&C[(r0+8)*T_DIM + n] = make_float2(acc[mt][nt][2], acc[mt][nt][3]);
        }
    }
}

// ================= fused HMMA attention (ac + G-gather + softmax + PV) =================
#define AST 72
#define O_QWH 0
#define O_QWL (O_QWH + 128*AST*2)
#define O_KTH (O_QWL + 128*AST*2)
#define O_KTL (O_KTH + 64*AST*2)
#define O_VTH (O_KTL + 64*AST*2)
#define O_VTL (O_VTH + 64*AST*2)
#define O_MASK (O_VTL + 64*AST*2)
#define ATTN_SMEM (O_MASK + 64)

__global__ __launch_bounds__(256, 2)
void attn_mma2(const unsigned char* __restrict__ mask,
               __nv_bfloat16* __restrict__ ctx_hi, __nv_bfloat16* __restrict__ ctx_lo) {
    extern __shared__ char smem[];
    __nv_bfloat16* qwh = (__nv_bfloat16*)(smem + O_QWH);
    __nv_bfloat16* qwl = (__nv_bfloat16*)(smem + O_QWL);
    __nv_bfloat16* kth = (__nv_bfloat16*)(smem + O_KTH);
    __nv_bfloat16* ktl = (__nv_bfloat16*)(smem + O_KTL);
    __nv_bfloat16* vth = (__nv_bfloat16*)(smem + O_VTH);
    __nv_bfloat16* vtl = (__nv_bfloat16*)(smem + O_VTL);
    unsigned char* smask = (unsigned char*)(smem + O_MASK);

    int tid = threadIdx.x;
    int wid = tid >> 5, lid = tid & 31;
    int gRow = lid >> 2, cPair = (lid & 3) * 2;
    int i0 = blockIdx.x * 128, h = blockIdx.y, b = blockIdx.z;
    int p = h*B_DIM + b;
    const float scale = 0.125f;

    const __nv_bfloat16* qwhp = g_qw_hi + (long)p*T_DIM*D_DIM;
    const __nv_bfloat16* qwlp = g_qw_lo + (long)p*T_DIM*D_DIM;
    const __nv_bfloat16* khp  = g_k_hi  + (long)p*T_DIM*D_DIM;
    const __nv_bfloat16* klp  = g_k_lo  + (long)p*T_DIM*D_DIM;
    const __nv_bfloat16* vhp  = g_vt_hi + (long)p*D_DIM*T_DIM;
    const __nv_bfloat16* vlp  = g_vt_lo + (long)p*D_DIM*T_DIM;
    const float* Gp = g_G + (long)p*T_DIM*T_DIM;

    // Q tile: 128 rows, direct uint4 copies
    for (int e = tid; e < 1024; e += 256) {
        int ii = e >> 3, q = e & 7;
        *(uint4*)&qwh[ii*AST + q*8] = *(const uint4*)&qwhp[(long)(i0+ii)*D_DIM + q*8];
        *(uint4*)&qwl[ii*AST + q*8] = *(const uint4*)&qwlp[(long)(i0+ii)*D_DIM + q*8];
    }

    float out[8][4];
#pragma unroll
    for (int nt = 0; nt < 8; nt++)
#pragma unroll
        for (int q = 0; q < 4; q++) out[nt][q] = 0.f;
    float mrow[2] = { -1e30f, -1e30f };
    float lrow[2] = { 0.f, 0.f };

    const int iir0 = wid*16 + gRow;

    for (int j0 = 0; j0 < T_DIM; j0 += 64) {
        __syncthreads();
        for (int e = tid; e < 512; e += 256) {
            int jj = e >> 3, q = e & 7;
            *(uint4*)&kth[jj*AST + q*8] = *(const uint4*)&khp[(long)(j0+jj)*D_DIM + q*8];
            *(uint4*)&ktl[jj*AST + q*8] = *(const uint4*)&klp[(long)(j0+jj)*D_DIM + q*8];
        }
        for (int e = tid; e < 512; e += 256) {
            int d = e >> 3, q = e & 7;
            *(uint4*)&vth[d*AST + q*8] = *(const uint4*)&vhp[(long)d*T_DIM + j0 + q*8];
            *(uint4*)&vtl[d*AST + q*8] = *(const uint4*)&vlp[(long)d*T_DIM + j0 + q*8];
        }
        if (tid < 64) smask[tid] = mask[b*T_DIM + j0 + tid];
        __syncthreads();

        // ac
        float sc[8][4];
#pragma unroll
        for (int nt = 0; nt < 8; nt++)
#pragma unroll
            for (int q = 0; q < 4; q++) sc[nt][q] = 0.f;
#pragma unroll
        for (int ks = 0; ks < 4; ks++) {
            int kb = ks*16;
            uint32_t ah[4], al[4];
            ah[0] = *(uint32_t*)&qwh[iir0*AST + kb + cPair];
            ah[1] = *(uint32_t*)&qwh[(iir0+8)*AST + kb + cPair];
            ah[2] = *(uint32_t*)&qwh[iir0*AST + kb + cPair + 8];
            ah[3] = *(uint32_t*)&qwh[(iir0+8)*AST + kb + cPair + 8];
            al[0] = *(uint32_t*)&qwl[iir0*AST + kb + cPair];
            al[1] = *(uint32_t*)&qwl[(iir0+8)*AST + kb + cPair];
            al[2] = *(uint32_t*)&qwl[iir0*AST + kb + cPair + 8];
            al[3] = *(uint32_t*)&qwl[(iir0+8)*AST + kb + cPair + 8];
#pragma unroll
            for (int nt = 0; nt < 8; nt++) {
                int nr = nt*8 + gRow;
                uint32_t bh[2], bl[2];
                bh[0] = *(uint32_t*)&kth[nr*AST + kb + cPair];
                bh[1] = *(uint32_t*)&kth[nr*AST + kb + cPair + 8];
                bl[0] = *(uint32_t*)&ktl[nr*AST + kb + cPair];
                bl[1] = *(uint32_t*)&ktl[nr*AST + kb + cPair + 8];
                mma16816(sc[nt], ah, bh);
                mma16816(sc[nt], ah, bl);
                mma16816(sc[nt], al, bh);
            }
        }

        // gather bd from G + scale + mask
#pragma unroll
        for (int nt = 0; nt < 8; nt++) {
#pragma unroll
            for (int q = 0; q < 4; q++) {
                int ii = iir0 + ((q >> 1) << 3);
                int jj = nt*8 + cPair + (q & 1);
                int i = i0 + ii, j = j0 + jj;
                int delta = j - i;
                float bdv;
                if (delta == 1)      bdv = 0.f;
                else if (delta <= 0) bdv = Gp[(long)i*T_DIM + (T_DIM-1+delta)];
                else                 bdv = Gp[(long)(i+1)*T_DIM + (delta-2)];
                float s = (sc[nt][q] + bdv) * scale;
                if (smask[jj]) s = -1e9f;
                sc[nt][q] = s;
            }
        }

        // online softmax
#pragma unroll
        for (int rr = 0; rr < 2; rr++) {
            float mx = -1e30f;
#pragma unroll
            for (int nt = 0; nt < 8; nt++)
                mx = fmaxf(mx, fmaxf(sc[nt][2*rr], sc[nt][2*rr+1]));
            mx = fmaxf(mx, __shfl_xor_sync(0xffffffffu, mx, 1));
            mx = fmaxf(mx, __shfl_xor_sync(0xffffffffu, mx, 2));
            float mnew = fmaxf(mrow[rr], mx);
            float corr = __expf(mrow[rr] - mnew);
            float rs = 0.f;
#pragma unroll
            for (int nt = 0; nt < 8; nt++) {
                float p0 = __expf(sc[nt][2*rr]   - mnew);
                float p1 = __expf(sc[nt][2*rr+1] - mnew);
                sc[nt][2*rr] = p0; sc[nt][2*rr+1] = p1;
                rs += p0 + p1;
            }
            rs += __shfl_xor_sync(0xffffffffu, rs, 1);
            rs += __shfl_xor_sync(0xffffffffu, rs, 2);
            lrow[rr] = lrow[rr]*corr + rs;
            mrow[rr] = mnew;
#pragma unroll
            for (int nt = 0; nt < 8; nt++) {
                out[nt][2*rr]   *= corr;
                out[nt][2*rr+1] *= corr;
            }
        }

        // PV
#pragma unroll
        for (int ks = 0; ks < 4; ks++) {
            int t0 = 2*ks, t1 = 2*ks + 1;
            uint32_t pah[4], pal[4];
            split2(sc[t0][0], sc[t0][1], pah[0], pal[0]);
            split2(sc[t0][2], sc[t0][3], pah[1], pal[1]);
            split2(sc[t1][0], sc[t1][1], pah[2], pal[2]);
            split2(sc[t1][2], sc[t1][3], pah[3], pal[3]);
            int kb = ks*16;
#pragma unroll
            for (int nt = 0; nt < 8; nt++) {
                int nr = nt*8 + gRow;
                uint32_t bh[2], bl[2];
                bh[0] = *(uint32_t*)&vth[nr*AST + kb + cPair];
                bh[1] = *(uint32_t*)&vth[nr*AST + kb + cPair + 8];
                bl[0] = *(uint32_t*)&vtl[nr*AST + kb + cPair];
                bl[1] = *(uint32_t*)&vtl[nr*AST + kb + cPair + 8];
                mma16816(out[nt], pah, bh);
                mma16816(out[nt], pah, bl);
                mma16816(out[nt], pal, bh);
            }
        }
    }

    float inv0 = 1.f / lrow[0], inv1 = 1.f / lrow[1];
    int t0 = i0 + iir0, t1 = t0 + 8;
#pragma unroll
    for (int nt = 0; nt < 8; nt++) {
        long o0 = (long)(t0*B_DIM + b)*E_DIM + h*D_DIM + nt*8 + cPair;
        long o1 = (long)(t1*B_DIM + b)*E_DIM + h*D_DIM + nt*8 + cPair;
        uint32_t hi, lo;
        split2(out[nt][0]*inv0, out[nt][1]*inv0, hi, lo);
        *(uint32_t*)&ctx_hi[o0] = hi; *(uint32_t*)&ctx_lo[o0] = lo;
        split2(out[nt][2]*inv1, out[nt][3]*inv1, hi, lo);
        *(uint32_t*)&ctx_hi[o1] = hi; *(uint32_t*)&ctx_lo[o1] = lo;
    }
}

extern "C" void kernel_launch(void* const* d_in, const int* in_sizes, int n_in,
                              void* d_out, int out_size) {
    const float* input   = (const float*)d_in[0];
    const float* pos     = (const float*)d_in[1];
    const int*   indices = (const int*)  d_in[2];
    const unsigned char* mask = (const unsigned char*)d_in[3];
    const float* in_w  = (const float*)d_in[4];
    const float* pos_w = (const float*)d_in[5];
    const float* out_w = (const float*)d_in[6];
    const float* in_b  = (const float*)d_in[7];
    const float* pos_b = (const float*)d_in[8];
    const float* out_b = (const float*)d_in[9];
    const float* r_i = (const float*)d_in[10];
    const float* s_i = (const float*)d_in[11];
    const float* r_p = (const float*)d_in[12];
    const float* s_p = (const float*)d_in[13];
    const float* r_o = (const float*)d_in[14];
    const float* s_o = (const float*)d_in[15];
    const float* rwb = (const float*)d_in[16];
    const float* rrb = (const float*)d_in[17];
    float* out = (float*)d_out;

    float *qkv, *rk;
    __nv_bfloat16 *in_hi, *in_lo, *pos_hi, *pos_lo, *ctx_hi, *ctx_lo;
    __nv_bfloat16 *win_hi, *win_lo, *wpos_hi, *wpos_lo, *wout_hi, *wout_lo;
    cudaGetSymbolAddress((void**)&qkv,   g_qkv);
    cudaGetSymbolAddress((void**)&rk,    g_rk);
    cudaGetSymbolAddress((void**)&in_hi, g_in_hi);
    cudaGetSymbolAddress((void**)&in_lo, g_in_lo);
    cudaGetSymbolAddress((void**)&pos_hi,g_pos_hi);
    cudaGetSymbolAddress((void**)&pos_lo,g_pos_lo);
    cudaGetSymbolAddress((void**)&ctx_hi,g_ctx_hi);
    cudaGetSymbolAddress((void**)&ctx_lo,g_ctx_lo);
    cudaGetSymbolAddress((void**)&win_hi,g_win_hi);
    cudaGetSymbolAddress((void**)&win_lo,g_win_lo);
    cudaGetSymbolAddress((void**)&wpos_hi,g_wpos_hi);
    cudaGetSymbolAddress((void**)&wpos_lo,g_wpos_lo);
    cudaGetSymbolAddress((void**)&wout_hi,g_wout_hi);
    cudaGetSymbolAddress((void**)&wout_lo,g_wout_lo);

    const int thr = 256;
    build_w_bf16<<<(E3*(E_DIM/8) + thr-1)/thr, thr>>>(in_w,  r_i, s_i, indices, win_hi,  win_lo,  E3);
    build_w_bf16<<<(E_DIM*(E_DIM/8) + thr-1)/thr, thr>>>(pos_w, r_p, s_p, indices, wpos_hi, wpos_lo, E_DIM);
    build_w_bf16<<<(E_DIM*(E_DIM/8) + thr-1)/thr, thr>>>(out_w, r_o, s_o, indices, wout_hi, wout_lo, E_DIM);
    conv_bf16<<<(T_DIM*B_DIM*E_DIM/4 + thr-1)/thr, thr>>>(input, in_hi, in_lo, T_DIM*B_DIM*E_DIM);
    conv_bf16<<<(T_DIM*E_DIM/4 + thr-1)/thr, thr>>>(pos, pos_hi, pos_lo, T_DIM*E_DIM);

    gemm_mma<<<dim3(E3/64, (T_DIM*B_DIM)/128), 256>>>(in_hi, in_lo, win_hi, win_lo, in_b, qkv, E3);
    gemm_mma<<<dim3(E_DIM/64, T_DIM/128), 256>>>(pos_hi, pos_lo, wpos_hi, wpos_lo, pos_b, rk, E_DIM);

    // packs
    prep_qkv<<<(NP*T_DIM*16 + thr-1)/thr, thr>>>(qkv, rwb, rrb);
    prep_v<<<dim3(T_DIM/64, NP), 256>>>(qkv);
    prep_rk<<<(H_DIM*T_DIM*16 + thr-1)/thr, thr>>>(rk);

    // G = qr @ rk^T per (h,b)
    cudaFuncSetAttribute(gemm_g, cudaFuncAttributeMaxDynamicSharedMemorySize, GG_SMEM);
    gemm_g<<<dim3(T_DIM/64, T_DIM/128, NP), 256, GG_SMEM>>>();

    cudaFuncSetAttribute(attn_mma2, cudaFuncAttributeMaxDynamicSharedMemorySize, ATTN_SMEM);
    attn_mma2<<<dim3(T_DIM/128, H_DIM, B_DIM), 256, ATTN_SMEM>>>(mask, ctx_hi, ctx_lo);

    gemm_mma<<<dim3(E_DIM/64, (T_DIM*B_DIM)/128), 256>>>(ctx_hi, ctx_lo, wout_hi, wout_lo, out_b, out, E_DIM);
}

// round 17
// speedup vs baseline: 1.6037x; 1.1017x over previous
#include <cuda_runtime.h>
#include <cuda_bf16.h>
#include <math.h>
#include <stdint.h>

#define T_DIM 1024
#define B_DIM 4
#define E_DIM 1024
#define H_DIM 16
#define D_DIM 64
#define RANK_ 4
#define E3 (3*E_DIM)
#define NP (B_DIM*H_DIM)

// ---- device scratch ----
__device__ float g_qkv  [T_DIM*B_DIM*E3];
__device__ float g_rk   [T_DIM*E_DIM];
__device__ float g_G    [(long)NP*T_DIM*T_DIM];

__device__ __align__(16) __nv_bfloat16 g_in_hi [T_DIM*B_DIM*E_DIM];
__device__ __align__(16) __nv_bfloat16 g_in_lo [T_DIM*B_DIM*E_DIM];
__device__ __align__(16) __nv_bfloat16 g_pos_hi[T_DIM*E_DIM];
__device__ __align__(16) __nv_bfloat16 g_pos_lo[T_DIM*E_DIM];
__device__ __align__(16) __nv_bfloat16 g_ctx_hi[T_DIM*B_DIM*E_DIM];
__device__ __align__(16) __nv_bfloat16 g_ctx_lo[T_DIM*B_DIM*E_DIM];
__device__ __align__(16) __nv_bfloat16 g_win_hi [E3*E_DIM];
__device__ __align__(16) __nv_bfloat16 g_win_lo [E3*E_DIM];
__device__ __align__(16) __nv_bfloat16 g_wpos_hi[E_DIM*E_DIM];
__device__ __align__(16) __nv_bfloat16 g_wpos_lo[E_DIM*E_DIM];
__device__ __align__(16) __nv_bfloat16 g_wout_hi[E_DIM*E_DIM];
__device__ __align__(16) __nv_bfloat16 g_wout_lo[E_DIM*E_DIM];
__device__ __align__(16) __nv_bfloat16 g_qw_hi[NP*T_DIM*D_DIM];
__device__ __align__(16) __nv_bfloat16 g_qw_lo[NP*T_DIM*D_DIM];
__device__ __align__(16) __nv_bfloat16 g_qr_hi[NP*T_DIM*D_DIM];
__device__ __align__(16) __nv_bfloat16 g_qr_lo[NP*T_DIM*D_DIM];
__device__ __align__(16) __nv_bfloat16 g_k_hi [NP*T_DIM*D_DIM];
__device__ __align__(16) __nv_bfloat16 g_k_lo [NP*T_DIM*D_DIM];
__device__ __align__(16) __nv_bfloat16 g_vt_hi[NP*D_DIM*T_DIM];
__device__ __align__(16) __nv_bfloat16 g_vt_lo[NP*D_DIM*T_DIM];
__device__ __align__(16) __nv_bfloat16 g_rkp_hi[H_DIM*T_DIM*D_DIM];
__device__ __align__(16) __nv_bfloat16 g_rkp_lo[H_DIM*T_DIM*D_DIM];

// ---- PTX helpers ----
__device__ __forceinline__ void mma16816(float* c, const uint32_t* a, const uint32_t* b){
    asm volatile(
        "mma.sync.aligned.m16n8k16.row.col.f32.bf16.bf16.f32 "
        "{%0,%1,%2,%3}, {%4,%5,%6,%7}, {%8,%9}, {%0,%1,%2,%3};"
        : "+f"(c[0]), "+f"(c[1]), "+f"(c[2]), "+f"(c[3])
        : "r"(a[0]), "r"(a[1]), "r"(a[2]), "r"(a[3]), "r"(b[0]), "r"(b[1]));
}
__device__ __forceinline__ uint32_t s2u32(const void* p){
    uint32_t a;
    asm("{ .reg .u64 t; cvta.to.shared.u64 t, %1; cvt.u32.u64 %0, t; }" : "=r"(a) : "l"(p));
    return a;
}
__device__ __forceinline__ void ldsm4(uint32_t* r, uint32_t a){
    asm volatile("ldmatrix.sync.aligned.m8n8.x4.shared.b16 {%0,%1,%2,%3}, [%4];"
        : "=r"(r[0]), "=r"(r[1]), "=r"(r[2]), "=r"(r[3]) : "r"(a));
}
__device__ __forceinline__ void split2(float a, float b, uint32_t& hi, uint32_t& lo){
    __nv_bfloat16 ah = __float2bfloat16(a), bh = __float2bfloat16(b);
    __nv_bfloat16 al = __float2bfloat16(a - __bfloat162float(ah));
    __nv_bfloat16 bl = __float2bfloat16(b - __bfloat162float(bh));
    __nv_bfloat162 H; H.x = ah; H.y = bh;
    __nv_bfloat162 L; L.x = al; L.y = bl;
    hi = *(uint32_t*)&H; lo = *(uint32_t*)&L;
}
__device__ __forceinline__ void put_hl(__nv_bfloat16* ph, __nv_bfloat16* pl, long idx, float v){
    __nv_bfloat16 h = __float2bfloat16(v);
    ph[idx] = h;
    pl[idx] = __float2bfloat16(v - __bfloat162float(h));
}

// lane offsets for ldmatrix address generation (elements; row-major [r][k] arrays)
// A x4: frag i covers rows {0-7,8-15}x k{0-7,8-15}: row = +(grp&1)*8+j, k = +(grp>>1)*8
// B x4: frag order (n0-7,k0-7),(n0-7,k8-15),(n8-15,k0-7),(n8-15,k8-15):
//        row = +(grp>>1)*8+j, k = +(grp&1)*8
#define A_LANE_ROW(lid) (((lid) & 7) + (((lid) >> 3) & 1) * 8)
#define A_LANE_K(lid)   ((((lid) >> 3) >> 1) * 8)
#define B_LANE_ROW(lid) (((lid) & 7) + (((lid) >> 3) >> 1) * 8)
#define B_LANE_K(lid)   ((((lid) >> 3) & 1) * 8)

// ---- W' = W + sum_r outer(r,s); TRANSPOSED [f][e] bf16 hi/lo ----
__global__ void build_w_bf16(const float* __restrict__ base, const float* __restrict__ rfac,
                             const float* __restrict__ sfac, const int* __restrict__ idx,
                             __nv_bfloat16* __restrict__ whi, __nv_bfloat16* __restrict__ wlo,
                             int F) {
    int lang = idx[0];
    long i = (long)blockIdx.x * blockDim.x + threadIdx.x;
    long total = (long)F * (E_DIM/8);
    if (i >= total) return;
    int f = (int)(i % F);
    int e0 = (int)(i / F) * 8;
    const float* rp = rfac + (long)lang * RANK_ * E_DIM;
    const float* sp = sfac + (long)lang * RANK_ * F;
    float sv[RANK_];
#pragma unroll
    for (int r = 0; r < RANK_; r++) sv[r] = sp[(long)r*F + f];
    __nv_bfloat16 h8[8], l8[8];
#pragma unroll
    for (int j = 0; j < 8; j++) {
        int e = e0 + j;
        float v = base[(long)e*F + f];
#pragma unroll
        for (int r = 0; r < RANK_; r++) v = fmaf(rp[r*E_DIM + e], sv[r], v);
        __nv_bfloat16 h = __float2bfloat16(v);
        h8[j] = h;
        l8[j] = __float2bfloat16(v - __bfloat162float(h));
    }
    *(uint4*)&whi[(long)f*E_DIM + e0] = *(uint4*)h8;
    *(uint4*)&wlo[(long)f*E_DIM + e0] = *(uint4*)l8;
}

// ---- fp32 -> bf16 hi/lo ----
__global__ void conv_bf16(const float* __restrict__ x, __nv_bfloat16* __restrict__ hi,
                          __nv_bfloat16* __restrict__ lo, int n) {
    int i = (blockIdx.x*blockDim.x + threadIdx.x) * 4;
    if (i >= n) return;
    float4 v = *(const float4*)&x[i];
    float vv[4] = {v.x, v.y, v.z, v.w};
    __nv_bfloat16 h4[4], l4[4];
#pragma unroll
    for (int j = 0; j < 4; j++) {
        __nv_bfloat16 h = __float2bfloat16(vv[j]);
        h4[j] = h;
        l4[j] = __float2bfloat16(vv[j] - __bfloat162float(h));
    }
    *(uint2*)&hi[i] = *(uint2*)h4;
    *(uint2*)&lo[i] = *(uint2*)l4;
}

// ---- HMMA bf16-split GEMM (ldmatrix fragment loads) ----
#define SA 56

__global__ __launch_bounds__(256, 2)
void gemm_mma(const __nv_bfloat16* __restrict__ Ahi, const __nv_bfloat16* __restrict__ Alo,
              const __nv_bfloat16* __restrict__ Bhi, const __nv_bfloat16* __restrict__ Blo,
              const float* __restrict__ bias, float* __restrict__ C, int N_) {
    __shared__ __align__(16) __nv_bfloat16 sAh[128*SA];
    __shared__ __align__(16) __nv_bfloat16 sAl[128*SA];
    __shared__ __align__(16) __nv_bfloat16 sBh[64*SA];
    __shared__ __align__(16) __nv_bfloat16 sBl[64*SA];

    const int K = E_DIM;
    int tid = threadIdx.x;
    int wid = tid >> 5, lid = tid & 31;
    int warpM = wid & 3, warpN = wid >> 2;
    long m0 = (long)blockIdx.y * 128, n0 = (long)blockIdx.x * 64;
    int gRow = lid >> 2, cPair = (lid & 3) * 2;

    const int ap0 = tid, ap1 = tid + 256;
    const int ar0 = ap0 >> 2, aq0 = ap0 & 3;
    const int ar1 = ap1 >> 2, aq1 = ap1 & 3;
    const int br = tid >> 2, bq = tid & 3;

    // ldmatrix lane bases (element offsets)
    const int aRow = A_LANE_ROW(lid), aK = A_LANE_K(lid);
    const int bRow = B_LANE_ROW(lid), bK = B_LANE_K(lid);
    uint32_t uAh = s2u32(sAh) + ((warpM*32 + aRow)*SA + aK) * 2;
    uint32_t uAl = s2u32(sAl) + ((warpM*32 + aRow)*SA + aK) * 2;
    uint32_t uBh = s2u32(sBh) + ((warpN*32 + bRow)*SA + bK) * 2;
    uint32_t uBl = s2u32(sBl) + ((warpN*32 + bRow)*SA + bK) * 2;

    float acc[2][4][4];
#pragma unroll
    for (int mt = 0; mt < 2; mt++)
#pragma unroll
        for (int nt = 0; nt < 4; nt++)
#pragma unroll
            for (int q = 0; q < 4; q++) acc[mt][nt][q] = 0.f;

    uint4 pah0 = *(const uint4*)&Ahi[(m0+ar0)*K + aq0*8];
    uint4 pah1 = *(const uint4*)&Ahi[(m0+ar1)*K + aq1*8];
    uint4 pal0 = *(const uint4*)&Alo[(m0+ar0)*K + aq0*8];
    uint4 pal1 = *(const uint4*)&Alo[(m0+ar1)*K + aq1*8];
    uint4 pbh  = *(const uint4*)&Bhi[(n0+br)*K + bq*8];
    uint4 pbl  = *(const uint4*)&Blo[(n0+br)*K + bq*8];

    for (int kc = 0; kc < K; kc += 32) {
        *(uint4*)&sAh[ar0*SA + aq0*8] = pah0;
        *(uint4*)&sAh[ar1*SA + aq1*8] = pah1;
        *(uint4*)&sAl[ar0*SA + aq0*8] = pal0;
        *(uint4*)&sAl[ar1*SA + aq1*8] = pal1;
        *(uint4*)&sBh[br*SA + bq*8] = pbh;
        *(uint4*)&sBl[br*SA + bq*8] = pbl;
        __syncthreads();
        if (kc + 32 < K) {
            int kn = kc + 32;
            pah0 = *(const uint4*)&Ahi[(m0+ar0)*K + kn + aq0*8];
            pah1 = *(const uint4*)&Ahi[(m0+ar1)*K + kn + aq1*8];
            pal0 = *(const uint4*)&Alo[(m0+ar0)*K + kn + aq0*8];
            pal1 = *(const uint4*)&Alo[(m0+ar1)*K + kn + aq1*8];
            pbh  = *(const uint4*)&Bhi[(n0+br)*K + kn + bq*8];
            pbl  = *(const uint4*)&Blo[(n0+br)*K + kn + bq*8];
        }
#pragma unroll
        for (int ks = 0; ks < 2; ks++) {
            int kb = ks * 16;
            uint32_t ah[2][4], al[2][4], bh[2][4], bl[2][4];
#pragma unroll
            for (int mt = 0; mt < 2; mt++) {
                ldsm4(ah[mt], uAh + (mt*16*SA + kb) * 2);
                ldsm4(al[mt], uAl + (mt*16*SA + kb) * 2);
            }
#pragma unroll
            for (int np = 0; np < 2; np++) {
                ldsm4(bh[np], uBh + (np*16*SA + kb) * 2);
                ldsm4(bl[np], uBl + (np*16*SA + kb) * 2);
            }
#pragma unroll
            for (int mt = 0; mt < 2; mt++)
#pragma unroll
                for (int nt = 0; nt < 4; nt++) {
                    const uint32_t* pbhf = &bh[nt>>1][(nt&1)*2];
                    const uint32_t* pblf = &bl[nt>>1][(nt&1)*2];
                    mma16816(acc[mt][nt], ah[mt], pbhf);
                    mma16816(acc[mt][nt], ah[mt], pblf);
                    mma16816(acc[mt][nt], al[mt], pbhf);
                }
        }
        __syncthreads();
    }
#pragma unroll
    for (int mt = 0; mt < 2; mt++) {
        long r0 = m0 + warpM*32 + mt*16 + gRow;
#pragma unroll
        for (int nt = 0; nt < 4; nt++) {
            long n = n0 + warpN*32 + nt*8 + cPair;
            float2 bia = *(const float2*)&bias[n];
            float2 o0 = { acc[mt][nt][0] + bia.x, acc[mt][nt][1] + bia.y };
            float2 o1 = { acc[mt][nt][2] + bia.x, acc[mt][nt][3] + bia.y };
            *(float2*)&C[r0*N_ + n] = o0;
            *(float2*)&C[(r0+8)*N_ + n] = o1;
        }
    }
}

// ---- prep: qkv -> qw/qr/k packs ----
__global__ void prep_qkv(const float* __restrict__ qkv,
                         const float* __restrict__ rwb, const float* __restrict__ rrb) {
    long gid = (long)blockIdx.x * blockDim.x + threadIdx.x;
    if (gid >= (long)NP*T_DIM*16) return;
    int d4 = (int)(gid & 15) * 4;
    int t  = (int)(gid >> 4) & (T_DIM-1);
    int p  = (int)(gid >> 14);
    int h = p >> 2, b = p & 3;
    long src = (long)(t*B_DIM + b)*E3 + h*D_DIM + d4;
    float4 qv = *(const float4*)&qkv[src];
    float4 kv = *(const float4*)&qkv[src + E_DIM];
    float4 wb = *(const float4*)&rwb[h*D_DIM + d4];
    float4 rb = *(const float4*)&rrb[h*D_DIM + d4];
    long dst = (long)p*T_DIM*D_DIM + (long)t*D_DIM + d4;
    float qvv[4] = {qv.x,qv.y,qv.z,qv.w};
    float kvv[4] = {kv.x,kv.y,kv.z,kv.w};
    float wbv[4] = {wb.x,wb.y,wb.z,wb.w};
    float rbv[4] = {rb.x,rb.y,rb.z,rb.w};
    __nv_bfloat16 a_h[4], a_l[4], r_h[4], r_l[4], k_h[4], k_l[4];
#pragma unroll
    for (int k = 0; k < 4; k++) {
        float a = qvv[k] + wbv[k];
        __nv_bfloat16 hh = __float2bfloat16(a);
        a_h[k] = hh; a_l[k] = __float2bfloat16(a - __bfloat162float(hh));
        float r = qvv[k] + rbv[k];
        hh = __float2bfloat16(r);
        r_h[k] = hh; r_l[k] = __float2bfloat16(r - __bfloat162float(hh));
        hh = __float2bfloat16(kvv[k]);
        k_h[k] = hh; k_l[k] = __float2bfloat16(kvv[k] - __bfloat162float(hh));
    }
    *(uint2*)&g_qw_hi[dst] = *(uint2*)a_h;  *(uint2*)&g_qw_lo[dst] = *(uint2*)a_l;
    *(uint2*)&g_qr_hi[dst] = *(uint2*)r_h;  *(uint2*)&g_qr_lo[dst] = *(uint2*)r_l;
    *(uint2*)&g_k_hi [dst] = *(uint2*)k_h;  *(uint2*)&g_k_lo [dst] = *(uint2*)k_l;
}

// ---- prep: V -> transposed packs [p][d][t] ----
__global__ void prep_v(const float* __restrict__ qkv) {
    __shared__ __nv_bfloat16 svh[64*68], svl[64*68];
    int tid = threadIdx.x;
    int t0 = blockIdx.x * 64;
    int p = blockIdx.y;
    int h = p >> 2, b = p & 3;
    for (int e = tid; e < 1024; e += 256) {
        int tt = e >> 4, d4 = (e & 15) * 4;
        long src = (long)((t0+tt)*B_DIM + b)*E3 + 2*E_DIM + h*D_DIM + d4;
        float4 v = *(const float4*)&qkv[src];
        float vv[4] = {v.x,v.y,v.z,v.w};
#pragma unroll
        for (int k = 0; k < 4; k++)
            put_hl(svh, svl, tt*68 + d4 + k, vv[k]);
    }
    __syncthreads();
    for (int e = tid; e < 1024; e += 256) {
        int d = e >> 4, t4 = (e & 15) * 4;
        __nv_bfloat16 oh[4], ol[4];
#pragma unroll
        for (int k = 0; k < 4; k++) {
            oh[k] = svh[(t4+k)*68 + d];
            ol[k] = svl[(t4+k)*68 + d];
        }
        long dst = (long)p*D_DIM*T_DIM + (long)d*T_DIM + t0 + t4;
        *(uint2*)&g_vt_hi[dst] = *(uint2*)oh;
        *(uint2*)&g_vt_lo[dst] = *(uint2*)ol;
    }
}

// ---- prep: rk -> [h][t][64] packs ----
__global__ void prep_rk(const float* __restrict__ rk) {
    long gid = (long)blockIdx.x * blockDim.x + threadIdx.x;
    if (gid >= (long)H_DIM*T_DIM*16) return;
    int d4 = (int)(gid & 15) * 4;
    int t  = (int)(gid >> 4) & (T_DIM-1);
    int h  = (int)(gid >> 14);
    float4 v = *(const float4*)&rk[(long)t*E_DIM + h*D_DIM + d4];
    float vv[4] = {v.x,v.y,v.z,v.w};
    long dst = (long)h*T_DIM*D_DIM + (long)t*D_DIM + d4;
    __nv_bfloat16 oh[4], ol[4];
#pragma unroll
    for (int k = 0; k < 4; k++) {
        __nv_bfloat16 hh = __float2bfloat16(vv[k]);
        oh[k] = hh; ol[k] = __float2bfloat16(vv[k] - __bfloat162float(hh));
    }
    *(uint2*)&g_rkp_hi[dst] = *(uint2*)oh;
    *(uint2*)&g_rkp_lo[dst] = *(uint2*)ol;
}

// ---- G GEMM (ldmatrix) ----
#define GSA 72
#define GG_SMEM ((128*GSA + 64*GSA) * 2 * 2)

__global__ __launch_bounds__(256, 2)
void gemm_g() {
    extern __shared__ __nv_bfloat16 gsm[];
    __nv_bfloat16* sAh = gsm;
    __nv_bfloat16* sAl = sAh + 128*GSA;
    __nv_bfloat16* sBh = sAl + 128*GSA;
    __nv_bfloat16* sBl = sBh + 64*GSA;

    int tid = threadIdx.x;
    int wid = tid >> 5, lid = tid & 31;
    int warpM = wid & 3, warpN = wid >> 2;
    int gRow = lid >> 2, cPair = (lid & 3) * 2;
    int p = blockIdx.z;
    long m0 = (long)blockIdx.y * 128, n0 = (long)blockIdx.x * 64;
    const __nv_bfloat16* Ah = g_qr_hi + (long)p*T_DIM*D_DIM;
    const __nv_bfloat16* Al = g_qr_lo + (long)p*T_DIM*D_DIM;
    const __nv_bfloat16* Bh = g_rkp_hi + (long)(p >> 2)*T_DIM*D_DIM;
    const __nv_bfloat16* Bl = g_rkp_lo + (long)(p >> 2)*T_DIM*D_DIM;
    float* C = g_G + (long)p*T_DIM*T_DIM;

    for (int e = tid; e < 1024; e += 256) {
        int r = e >> 3, q = e & 7;
        *(uint4*)&sAh[r*GSA + q*8] = *(const uint4*)&Ah[(m0+r)*D_DIM + q*8];
        *(uint4*)&sAl[r*GSA + q*8] = *(const uint4*)&Al[(m0+r)*D_DIM + q*8];
    }
    for (int e = tid; e < 512; e += 256) {
        int r = e >> 3, q = e & 7;
        *(uint4*)&sBh[r*GSA + q*8] = *(const uint4*)&Bh[(n0+r)*D_DIM + q*8];
        *(uint4*)&sBl[r*GSA + q*8] = *(const uint4*)&Bl[(n0+r)*D_DIM + q*8];
    }
    __syncthreads();

    const int aRow = A_LANE_ROW(lid), aK = A_LANE_K(lid);
    const int bRow = B_LANE_ROW(lid), bK = B_LANE_K(lid);
    uint32_t uAh = s2u32(sAh) + ((warpM*32 + aRow)*GSA + aK) * 2;
    uint32_t uAl = s2u32(sAl) + ((warpM*32 + aRow)*GSA + aK) * 2;
    uint32_t uBh = s2u32(sBh) + ((warpN*32 + bRow)*GSA + bK) * 2;
    uint32_t uBl = s2u32(sBl) + ((warpN*32 + bRow)*GSA + bK) * 2;

    float acc[2][4][4];
#pragma unroll
    for (int mt = 0; mt < 2; mt++)
#pragma unroll
        for (int nt = 0; nt < 4; nt++)
#pragma unroll
            for (int q = 0; q < 4; q++) acc[mt][nt][q] = 0.f;

#pragma unroll
    for (int ks = 0; ks < 4; ks++) {
        int kb = ks * 16;
        uint32_t ah[2][4], al[2][4], bh[2][4], bl[2][4];
#pragma unroll
        for (int mt = 0; mt < 2; mt++) {
            ldsm4(ah[mt], uAh + (mt*16*GSA + kb) * 2);
            ldsm4(al[mt], uAl + (mt*16*GSA + kb) * 2);
        }
#pragma unroll
        for (int np = 0; np < 2; np++) {
            ldsm4(bh[np], uBh + (np*16*GSA + kb) * 2);
            ldsm4(bl[np], uBl + (np*16*GSA + kb) * 2);
        }
#pragma unroll
        for (int mt = 0; mt < 2; mt++)
#pragma unroll
            for (int nt = 0; nt < 4; nt++) {
                const uint32_t* pbhf = &bh[nt>>1][(nt&1)*2];
                const uint32_t* pblf = &bl[nt>>1][(nt&1)*2];
                mma16816(acc[mt][nt], ah[mt], pbhf);
                mma16816(acc[mt][nt], ah[mt], pblf);
                mma16816(acc[mt][nt], al[mt], pbhf);
            }
    }
#pragma unroll
    for (int mt = 0; mt < 2; mt++) {
        long r0 = m0 + warpM*32 + mt*16 + gRow;
#pragma unroll
        for (int nt = 0; nt < 4; nt++) {
            long n = n0 + warpN*32 + nt*8 + cPair;
            *(float2*)&C[r0*T_DIM + n] = make_float2(acc[mt][nt][0], acc[mt][nt][1]);
            *(float2*)&C[(r0+8)*T_DIM + n] = make_float2(acc[mt][nt][2], acc[mt][nt][3]);
        }
    }
}

// ================= fused HMMA attention (ldmatrix) =================
#define AST 72
#define O_QWH 0
#define O_QWL (O_QWH + 128*AST*2)
#define O_KTH (O_QWL + 128*AST*2)
#define O_KTL (O_KTH + 64*AST*2)
#define O_VTH (O_KTL + 64*AST*2)
#define O_VTL (O_VTH + 64*AST*2)
#define O_MASK (O_VTL + 64*AST*2)
#define ATTN_SMEM (O_MASK + 64)

__global__ __launch_bounds__(256, 2)
void attn_mma2(const unsigned char* __restrict__ mask,
               __nv_bfloat16* __restrict__ ctx_hi, __nv_bfloat16* __restrict__ ctx_lo) {
    extern __shared__ char smem[];
    __nv_bfloat16* qwh = (__nv_bfloat16*)(smem + O_QWH);
    __nv_bfloat16* qwl = (__nv_bfloat16*)(smem + O_QWL);
    __nv_bfloat16* kth = (__nv_bfloat16*)(smem + O_KTH);
    __nv_bfloat16* ktl = (__nv_bfloat16*)(smem + O_KTL);
    __nv_bfloat16* vth = (__nv_bfloat16*)(smem + O_VTH);
    __nv_bfloat16* vtl = (__nv_bfloat16*)(smem + O_VTL);
    unsigned char* smask = (unsigned char*)(smem + O_MASK);

    int tid = threadIdx.x;
    int wid = tid >> 5, lid = tid & 31;
    int gRow = lid >> 2, cPair = (lid & 3) * 2;
    int i0 = blockIdx.x * 128, h = blockIdx.y, b = blockIdx.z;
    int p = h*B_DIM + b;
    const float scale = 0.125f;

    const __nv_bfloat16* qwhp = g_qw_hi + (long)p*T_DIM*D_DIM;
    const __nv_bfloat16* qwlp = g_qw_lo + (long)p*T_DIM*D_DIM;
    const __nv_bfloat16* khp  = g_k_hi  + (long)p*T_DIM*D_DIM;
    const __nv_bfloat16* klp  = g_k_lo  + (long)p*T_DIM*D_DIM;
    const __nv_bfloat16* vhp  = g_vt_hi + (long)p*D_DIM*T_DIM;
    const __nv_bfloat16* vlp  = g_vt_lo + (long)p*D_DIM*T_DIM;
    const float* Gp = g_G + (long)p*T_DIM*T_DIM;

    for (int e = tid; e < 1024; e += 256) {
        int ii = e >> 3, q = e & 7;
        *(uint4*)&qwh[ii*AST + q*8] = *(const uint4*)&qwhp[(long)(i0+ii)*D_DIM + q*8];
        *(uint4*)&qwl[ii*AST + q*8] = *(const uint4*)&qwlp[(long)(i0+ii)*D_DIM + q*8];
    }

    const int aRow = A_LANE_ROW(lid), aK = A_LANE_K(lid);
    const int bRow = B_LANE_ROW(lid), bK = B_LANE_K(lid);
    uint32_t uQh = s2u32(qwh) + ((wid*16 + aRow)*AST + aK) * 2;
    uint32_t uQl = s2u32(qwl) + ((wid*16 + aRow)*AST + aK) * 2;
    uint32_t uKh = s2u32(kth) + (bRow*AST + bK) * 2;
    uint32_t uKl = s2u32(ktl) + (bRow*AST + bK) * 2;
    uint32_t uVh = s2u32(vth) + (bRow*AST + bK) * 2;
    uint32_t uVl = s2u32(vtl) + (bRow*AST + bK) * 2;

    float out[8][4];
#pragma unroll
    for (int nt = 0; nt < 8; nt++)
#pragma unroll
        for (int q = 0; q < 4; q++) out[nt][q] = 0.f;
    float mrow[2] = { -1e30f, -1e30f };
    float lrow[2] = { 0.f, 0.f };

    const int iir0 = wid*16 + gRow;

    for (int j0 = 0; j0 < T_DIM; j0 += 64) {
        __syncthreads();
        for (int e = tid; e < 512; e += 256) {
            int jj = e >> 3, q = e & 7;
            *(uint4*)&kth[jj*AST + q*8] = *(const uint4*)&khp[(long)(j0+jj)*D_DIM + q*8];
            *(uint4*)&ktl[jj*AST + q*8] = *(const uint4*)&klp[(long)(j0+jj)*D_DIM + q*8];
        }
        for (int e = tid; e < 512; e += 256) {
            int d = e >> 3, q = e & 7;
            *(uint4*)&vth[d*AST + q*8] = *(const uint4*)&vhp[(long)d*T_DIM + j0 + q*8];
            *(uint4*)&vtl[d*AST + q*8] = *(const uint4*)&vlp[(long)d*T_DIM + j0 + q*8];
        }
        if (tid < 64) smask[tid] = mask[b*T_DIM + j0 + tid];
        __syncthreads();

        // ac
        float sc[8][4];
#pragma unroll
        for (int nt = 0; nt < 8; nt++)
#pragma unroll
            for (int q = 0; q < 4; q++) sc[nt][q] = 0.f;
#pragma unroll
        for (int ks = 0; ks < 4; ks++) {
            int kb = ks*16;
            uint32_t ah[4], al[4], bh[4][4], bl[4][4];
            ldsm4(ah, uQh + kb*2);
            ldsm4(al, uQl + kb*2);
#pragma unroll
            for (int np = 0; np < 4; np++) {
                ldsm4(bh[np], uKh + (np*16*AST + kb) * 2);
                ldsm4(bl[np], uKl + (np*16*AST + kb) * 2);
            }
#pragma unroll
            for (int nt = 0; nt < 8; nt++) {
                const uint32_t* pbhf = &bh[nt>>1][(nt&1)*2];
                const uint32_t* pblf = &bl[nt>>1][(nt&1)*2];
                mma16816(sc[nt], ah, pbhf);
                mma16816(sc[nt], ah, pblf);
                mma16816(sc[nt], al, pbhf);
            }
        }

        // gather bd from G + scale + mask
#pragma unroll
        for (int nt = 0; nt < 8; nt++) {
#pragma unroll
            for (int q = 0; q < 4; q++) {
                int ii = iir0 + ((q >> 1) << 3);
                int jj = nt*8 + cPair + (q & 1);
                int i = i0 + ii, j = j0 + jj;
                int delta = j - i;
                float bdv;
                if (delta == 1)      bdv = 0.f;
                else if (delta <= 0) bdv = Gp[(long)i*T_DIM + (T_DIM-1+delta)];
                else                 bdv = Gp[(long)(i+1)*T_DIM + (delta-2)];
                float s = (sc[nt][q] + bdv) * scale;
                if (smask[jj]) s = -1e9f;
                sc[nt][q] = s;
            }
        }

        // online softmax
#pragma unroll
        for (int rr = 0; rr < 2; rr++) {
            float mx = -1e30f;
#pragma unroll
            for (int nt = 0; nt < 8; nt++)
                mx = fmaxf(mx, fmaxf(sc[nt][2*rr], sc[nt][2*rr+1]));
            mx = fmaxf(mx, __shfl_xor_sync(0xffffffffu, mx, 1));
            mx = fmaxf(mx, __shfl_xor_sync(0xffffffffu, mx, 2));
            float mnew = fmaxf(mrow[rr], mx);
            float corr = __expf(mrow[rr] - mnew);
            float rs = 0.f;
#pragma unroll
            for (int nt = 0; nt < 8; nt++) {
                float p0 = __expf(sc[nt][2*rr]   - mnew);
                float p1 = __expf(sc[nt][2*rr+1] - mnew);
                sc[nt][2*rr] = p0; sc[nt][2*rr+1] = p1;
                rs += p0 + p1;
            }
            rs += __shfl_xor_sync(0xffffffffu, rs, 1);
            rs += __shfl_xor_sync(0xffffffffu, rs, 2);
            lrow[rr] = lrow[rr]*corr + rs;
            mrow[rr] = mnew;
#pragma unroll
            for (int nt = 0; nt < 8; nt++) {
                out[nt][2*rr]   *= corr;
                out[nt][2*rr+1] *= corr;
            }
        }

        // PV
#pragma unroll
        for (int ks = 0; ks < 4; ks++) {
            int t0 = 2*ks, t1 = 2*ks + 1;
            uint32_t pah[4], pal[4];
            split2(sc[t0][0], sc[t0][1], pah[0], pal[0]);
            split2(sc[t0][2], sc[t0][3], pah[1], pal[1]);
            split2(sc[t1][0], sc[t1][1], pah[2], pal[2]);
            split2(sc[t1][2], sc[t1][3], pah[3], pal[3]);
            int kb = ks*16;
            uint32_t bh[4][4], bl[4][4];
#pragma unroll
            for (int np = 0; np < 4; np++) {
                ldsm4(bh[np], uVh + (np*16*AST + kb) * 2);
                ldsm4(bl[np], uVl + (np*16*AST + kb) * 2);
            }
#pragma unroll
            for (int nt = 0; nt < 8; nt++) {
                const uint32_t* pbhf = &bh[nt>>1][(nt&1)*2];
                const uint32_t* pblf = &bl[nt>>1][(nt&1)*2];
                mma16816(out[nt], pah, pbhf);
                mma16816(out[nt], pah, pblf);
                mma16816(out[nt], pal, pbhf);
            }
        }
    }

    float inv0 = 1.f / lrow[0], inv1 = 1.f / lrow[1];
    int t0 = i0 + iir0, t1 = t0 + 8;
#pragma unroll
    for (int nt = 0; nt < 8; nt++) {
        long o0 = (long)(t0*B_DIM + b)*E_DIM + h*D_DIM + nt*8 + cPair;
        long o1 = (long)(t1*B_DIM + b)*E_DIM + h*D_DIM + nt*8 + cPair;
        uint32_t hi, lo;
        split2(out[nt][0]*inv0, out[nt][1]*inv0, hi, lo);
        *(uint32_t*)&ctx_hi[o0] = hi; *(uint32_t*)&ctx_lo[o0] = lo;
        split2(out[nt][2]*inv1, out[nt][3]*inv1, hi, lo);
        *(uint32_t*)&ctx_hi[o1] = hi; *(uint32_t*)&ctx_lo[o1] = lo;
    }
}

extern "C" void kernel_launch(void* const* d_in, const int* in_sizes, int n_in,
                              void* d_out, int out_size) {
    const float* input   = (const float*)d_in[0];
    const float* pos     = (const float*)d_in[1];
    const int*   indices = (const int*)  d_in[2];
    const unsigned char* mask = (const unsigned char*)d_in[3];
    const float* in_w  = (const float*)d_in[4];
    const float* pos_w = (const float*)d_in[5];
    const float* out_w = (const float*)d_in[6];
    const float* in_b  = (const float*)d_in[7];
    const float* pos_b = (const float*)d_in[8];
    const float* out_b = (const float*)d_in[9];
    const float* r_i = (const float*)d_in[10];
    const float* s_i = (const float*)d_in[11];
    const float* r_p = (const float*)d_in[12];
    const float* s_p = (const float*)d_in[13];
    const float* r_o = (const float*)d_in[14];
    const float* s_o = (const float*)d_in[15];
    const float* rwb = (const float*)d_in[16];
    const float* rrb = (const float*)d_in[17];
    float* out = (float*)d_out;

    float *qkv, *rk;
    __nv_bfloat16 *in_hi, *in_lo, *pos_hi, *pos_lo, *ctx_hi, *ctx_lo;
    __nv_bfloat16 *win_hi, *win_lo, *wpos_hi, *wpos_lo, *wout_hi, *wout_lo;
    cudaGetSymbolAddress((void**)&qkv,   g_qkv);
    cudaGetSymbolAddress((void**)&rk,    g_rk);
    cudaGetSymbolAddress((void**)&in_hi, g_in_hi);
    cudaGetSymbolAddress((void**)&in_lo, g_in_lo);
    cudaGetSymbolAddress((void**)&pos_hi,g_pos_hi);
    cudaGetSymbolAddress((void**)&pos_lo,g_pos_lo);
    cudaGetSymbolAddress((void**)&ctx_hi,g_ctx_hi);
    cudaGetSymbolAddress((void**)&ctx_lo,g_ctx_lo);
    cudaGetSymbolAddress((void**)&win_hi,g_win_hi);
    cudaGetSymbolAddress((void**)&win_lo,g_win_lo);
    cudaGetSymbolAddress((void**)&wpos_hi,g_wpos_hi);
    cudaGetSymbolAddress((void**)&wpos_lo,g_wpos_lo);
    cudaGetSymbolAddress((void**)&wout_hi,g_wout_hi);
    cudaGetSymbolAddress((void**)&wout_lo,g_wout_lo);

    const int thr = 256;
    build_w_bf16<<<(E3*(E_DIM/8) + thr-1)/thr, thr>>>(in_w,  r_i, s_i, indices, win_hi,  win_lo,  E3);
    build_w_bf16<<<(E_DIM*(E_DIM/8) + thr-1)/thr, thr>>>(pos_w, r_p, s_p, indices, wpos_hi, wpos_lo, E_DIM);
    build_w_bf16<<<(E_DIM*(E_DIM/8) + thr-1)/thr, thr>>>(out_w, r_o, s_o, indices, wout_hi, wout_lo, E_DIM);
    conv_bf16<<<(T_DIM*B_DIM*E_DIM/4 + thr-1)/thr, thr>>>(input, in_hi, in_lo, T_DIM*B_DIM*E_DIM);
    conv_bf16<<<(T_DIM*E_DIM/4 + thr-1)/thr, thr>>>(pos, pos_hi, pos_lo, T_DIM*E_DIM);

    gemm_mma<<<dim3(E3/64, (T_DIM*B_DIM)/128), 256>>>(in_hi, in_lo, win_hi, win_lo, in_b, qkv, E3);
    gemm_mma<<<dim3(E_DIM/64, T_DIM/128), 256>>>(pos_hi, pos_lo, wpos_hi, wpos_lo, pos_b, rk, E_DIM);

    prep_qkv<<<(NP*T_DIM*16 + thr-1)/thr, thr>>>(qkv, rwb, rrb);
    prep_v<<<dim3(T_DIM/64, NP), 256>>>(qkv);
    prep_rk<<<(H_DIM*T_DIM*16 + thr-1)/thr, thr>>>(rk);

    cudaFuncSetAttribute(gemm_g, cudaFuncAttributeMaxDynamicSharedMemorySize, GG_SMEM);
    gemm_g<<<dim3(T_DIM/64, T_DIM/128, NP), 256, GG_SMEM>>>();

    cudaFuncSetAttribute(attn_mma2, cudaFuncAttributeMaxDynamicSharedMemorySize, ATTN_SMEM);
    attn_mma2<<<dim3(T_DIM/128, H_DIM, B_DIM), 256, ATTN_SMEM>>>(mask, ctx_hi, ctx_lo);

    gemm_mma<<<dim3(E_DIM/64, (T_DIM*B_DIM)/128), 256>>>(ctx_hi, ctx_lo, wout_hi, wout_lo, out_b, out, E_DIM);
}